// round 12
// baseline (speedup 1.0000x reference)
#include <cuda_runtime.h>
#include <cuda_fp16.h>
#include <stdint.h>
#include <math.h>

#define BB 32
#define TT 10

// ---------------- scratch (device globals; no allocs allowed) ----------------
__device__ float          g_e1 [320 * 16 * 64 * 64];   // encoder conv1 out (fp32)
__device__ unsigned short g_e2p[320 * 64 * 1024];      // encoder conv2 out (fp16 bits)
__device__ float          g_h  [BB * 64 * 1024];       // GRU hidden (fp32 master)
__device__ unsigned short g_hp [BB * 64 * 1024];       // h (fp16 bits)
__device__ float          g_z  [BB * 64 * 1024];       // z gate (fp32)
__device__ unsigned short g_rhp[BB * 64 * 1024];       // r*h (fp16 bits)
__device__ unsigned short g_hsp[TT * BB * 64 * 1024];  // decoder hidden outputs (fp16 bits)
__device__ float          g_y1 [320 * 32 * 64 * 64];   // deconv1 out (fp32)
__device__ float          g_uzr[320 * 128 * 1024];     // precomputed enc x-part of zr (+bias)
__device__ float          g_uc [320 * 64 * 1024];      // precomputed enc x-part of cand (+bias)
__device__ __align__(16) unsigned short g_wp [921600]; // GRU W fragments, fp16 (6 regions)
__device__ __align__(16) unsigned short g_wd1[32768];  // deconv1 W fragments, fp16

__device__ __forceinline__ unsigned short h16(float v) {
    return __half_as_ushort(__float2half(v));
}

// ---------------- fused init: zero h/hp + pack GRU weight regions + deconv1 weights ----------------
// GRU regions (each [tap][kc=4][ob][lane][r][e], IC-half of 64):
//  0: enc zr x-part   (OC=128, ic 0:64)    off 0
//  1: enc zr h-part   (OC=128, ic 64:128)  off 204800
//  2: enc c  x-part   (OC=64,  ic 0:64)    off 409600
//  3: enc c  rh-part  (OC=64,  ic 64:128)  off 512000
//  4: dec zr h-part   (OC=128, ic 64:128)  off 614400
//  5: dec c  rh-part  (OC=64,  ic 64:128)  off 819200
__global__ void init_all(const float* __restrict__ ewzr, const float* __restrict__ ewc,
                         const float* __restrict__ dwzr, const float* __restrict__ dwc,
                         const float* __restrict__ dw1) {
    long lidx = (long)blockIdx.x * 256 + threadIdx.x;
    if (lidx < 2097152) { g_h[lidx] = 0.f; g_hp[lidx] = 0; return; }
    int idx = (int)(lidx - 2097152);
    if (idx >= 921600) {
        // deconv1 weights: [p][tt][kc][ob][lane][r][e]
        int id = idx - 921600;
        if (id >= 32768) return;
        int e    = id & 1;
        int r    = (id >> 1) & 3;
        int lane = (id >> 3) & 31;
        int ob   = (id >> 8) & 1;
        int kc   = (id >> 9) & 3;
        int tt   = (id >> 11) & 3;
        int p    = (id >> 13) & 3;
        int g = lane >> 2, tg = lane & 3;
        int oc = ob * 16 + g + 8 * (r & 1);
        int ic = kc * 16 + 2 * tg + 8 * (r >> 1) + e;
        int a = p >> 1, bb = p & 1, jy = tt >> 1, jx = tt & 1;
        int kidx = (a + 2 * jy) * 4 + (bb + 2 * jx);
        g_wd1[id] = h16(dw1[(oc * 64 + ic) * 16 + kidx]);
        return;
    }
    const float* w; int NOB, icoff, dofs;
    if (idx < 204800)      { w = ewzr; NOB = 8; icoff = 0;  dofs = 0; }
    else if (idx < 409600) { idx -= 204800; w = ewzr; NOB = 8; icoff = 64; dofs = 204800; }
    else if (idx < 512000) { idx -= 409600; w = ewc;  NOB = 4; icoff = 0;  dofs = 409600; }
    else if (idx < 614400) { idx -= 512000; w = ewc;  NOB = 4; icoff = 64; dofs = 512000; }
    else if (idx < 819200) { idx -= 614400; w = dwzr; NOB = 8; icoff = 64; dofs = 614400; }
    else                   { idx -= 819200; w = dwc;  NOB = 4; icoff = 64; dofs = 819200; }
    int e    = idx & 1;
    int r    = (idx >> 1) & 3;
    int lane = (idx >> 3) & 31;
    int v    = idx >> 8;
    int ob   = v % NOB;
    int v2   = v / NOB;
    int kc   = v2 & 3;
    int tap  = v2 >> 2;
    int g = lane >> 2, tg = lane & 3;
    int oc = ob * 16 + g + 8 * (r & 1);
    int ic = icoff + kc * 16 + 2 * tg + 8 * (r >> 1) + e;
    g_wp[dofs + idx] = h16(w[(oc * 128 + ic) * 25 + tap]);
}

// ---------------- mma helper (fp16 in, fp32 accum) ----------------
__device__ __forceinline__ void mma_f16(float (&d)[4], const uint4& a, const unsigned (&b)[2]) {
    asm volatile(
        "mma.sync.aligned.m16n8k16.row.col.f32.f16.f16.f32 "
        "{%0,%1,%2,%3}, {%4,%5,%6,%7}, {%8,%9}, {%0,%1,%2,%3};\n"
        : "+f"(d[0]), "+f"(d[1]), "+f"(d[2]), "+f"(d[3])
        : "r"(a.x), "r"(a.y), "r"(a.z), "r"(a.w), "r"(b[0]), "r"(b[1]));
}

// ---------------- unified GRU-family 5x5 conv (IC=64) via mma.sync fp16 ----------------
// mode 0: batch enc zr x-part  (x=e2p[n], n=blockIdx.x)  -> g_uzr raw + bias
// mode 1: batch enc c  x-part  (x=e2p[n])                -> g_uc  raw + bias
// mode 2: enc zr step  (x=hp[b])   epil: sigmoid(D+U)  -> r*h / z
// mode 3: enc c  step  (x=rhp[b])  epil: tanh(D+U)     -> h update
// mode 4: dec zr step  (x=hp[b])   epil: sigmoid(D+b)  -> r*h / z
// mode 5: dec c  step  (x=rhp[b])  epil: tanh(D+b)     -> h update + g_hsp
__global__ __launch_bounds__(256, 2) void gru2(int t, int mode, int nob, int wofs,
                                               const float* __restrict__ bias) {
    extern __shared__ unsigned short Xs[];   // [288 px][72] fp16 bits

    int bx  = blockIdx.x;
    int y0  = blockIdx.y * 4;
    int och = blockIdx.z;
    int tid = threadIdx.x;
    int w   = tid >> 5, lane = tid & 31;
    int g   = lane >> 2, tg = lane & 3;
    int mw  = w >> 2, nw = w & 3;

    const unsigned short* base;
    if (mode <= 1)      base = g_e2p + bx * 65536;
    else if (mode == 2 || mode == 4) base = g_hp  + bx * 65536;
    else                base = g_rhp + bx * 65536;

    // ---- stage 64-ch tile: [sy 0..7][sx 0..35][c] ----
    {
        int c = tid & 63;
#pragma unroll
        for (int it = 0; it < 2; it++) {
            int sy = (tid >> 6) | (it << 2);
            int yy = y0 - 2 + sy;
            bool rv = (unsigned)yy < 32u;
            const uint4* src = (const uint4*)(base + c * 1024 + yy * 32);
            uint4 q[4];
            if (rv) {
#pragma unroll
                for (int k2 = 0; k2 < 4; k2++) q[k2] = src[k2];
            } else {
#pragma unroll
                for (int k2 = 0; k2 < 4; k2++) q[k2] = make_uint4(0u, 0u, 0u, 0u);
            }
            const unsigned short* hv = (const unsigned short*)q;
            int rb = sy * 36;
#pragma unroll
            for (int sx = 0; sx < 36; sx++) {
                unsigned short v = (sx < 2 || sx >= 34) ? (unsigned short)0 : hv[sx - 2];
                Xs[(rb + sx) * 72 + c] = v;
            }
        }
    }
    __syncthreads();

    float D[2][4][4];
#pragma unroll
    for (int mt = 0; mt < 2; mt++)
#pragma unroll
        for (int nt = 0; nt < 4; nt++)
#pragma unroll
            for (int i = 0; i < 4; i++) D[mt][nt][i] = 0.f;

    const uint4* pw = reinterpret_cast<const uint4*>(g_wp) + (wofs >> 3);
    const int S1 = nob * 32;
    int fb = (och * 4 + mw * 2) * 32 + lane;
    uint4 ah[2];
#pragma unroll
    for (int mt = 0; mt < 2; mt++) ah[mt] = pw[fb + mt * 32];

#pragma unroll 1
    for (int tap = 0; tap < 25; tap++) {
        int dy = tap / 5, dx = tap - 5 * dy;
        int rowbase = ((nw + dy) * 36 + dx) * 72;
#pragma unroll
        for (int kch = 0; kch < 4; kch++) {
            int fn = (tap == 24 && kch == 3) ? fb : fb + S1;
            uint4 nah[2];
#pragma unroll
            for (int mt = 0; mt < 2; mt++) nah[mt] = pw[fn + mt * 32];
            unsigned Bs[4][2];
#pragma unroll
            for (int nt = 0; nt < 4; nt++) {
                int off = rowbase + (nt * 8 + g) * 72 + kch * 16 + 2 * tg;
                Bs[nt][0] = *(const unsigned*)(Xs + off);
                Bs[nt][1] = *(const unsigned*)(Xs + off + 8);
            }
#pragma unroll
            for (int mt = 0; mt < 2; mt++)
#pragma unroll
                for (int nt = 0; nt < 4; nt++) mma_f16(D[mt][nt], ah[mt], Bs[nt]);
#pragma unroll
            for (int mt = 0; mt < 2; mt++) ah[mt] = nah[mt];
            fb = fn;
        }
    }

    // ---- fused epilogue ----
    int y = y0 + nw;
#pragma unroll
    for (int mt = 0; mt < 2; mt++) {
#pragma unroll
        for (int ci2 = 0; ci2 < 2; ci2++) {
            int ocG = och * 64 + mw * 32 + mt * 16 + g + 8 * ci2;
#pragma unroll
            for (int nt = 0; nt < 4; nt++) {
#pragma unroll
                for (int j = 0; j < 2; j++) {
                    float acc = D[mt][nt][ci2 * 2 + j];
                    int   x   = nt * 8 + 2 * tg + j;
                    int   px  = y * 32 + x;
                    if (mode == 0) {
                        g_uzr[(bx * 128 + ocG) * 1024 + px] = acc + bias[ocG];
                    } else if (mode == 1) {
                        g_uc[(bx * 64 + ocG) * 1024 + px] = acc + bias[ocG];
                    } else if (mode == 2 || mode == 4) {
                        float pre = (mode == 2)
                            ? g_uzr[((bx * 10 + t) * 128 + ocG) * 1024 + px]
                            : bias[ocG];
                        float s = 1.f / (1.f + expf(-(acc + pre)));
                        if (ocG < 64) {
                            int hi = (bx * 64 + ocG) * 1024 + px;
                            g_rhp[hi] = h16(s * g_h[hi]);
                        } else {
                            g_z[(bx * 64 + ocG - 64) * 1024 + px] = s;
                        }
                    } else {
                        float pre = (mode == 3)
                            ? g_uc[((bx * 10 + t) * 64 + ocG) * 1024 + px]
                            : bias[ocG];
                        float c  = tanhf(acc + pre);
                        int   hi = (bx * 64 + ocG) * 1024 + px;
                        float z  = g_z[hi];
                        float hn = (1.f - z) * g_h[hi] + z * c;
                        g_h[hi]  = hn;
                        g_hp[hi] = h16(hn);
                        if (mode == 5) g_hsp[t * 2097152 + hi] = h16(hn);
                    }
                }
            }
        }
    }
}

// ---------------- deconv1 via mma.sync fp16: 64->32, 4x4 lhs_dil 2 pad 2, 4 parity 2x2 convs ----------------
__global__ __launch_bounds__(128) void deconv1_tc(const float* __restrict__ bias) {
    __shared__ unsigned short Xs[6 * 34 * 72];
    int n   = blockIdx.x;
    int y0  = blockIdx.y * 4;
    int tid = threadIdx.x;
    int w   = tid >> 5, lane = tid & 31;
    int g   = lane >> 2, tg = lane & 3;
    int nw  = w;

    const unsigned short* in = g_hsp + n * 65536;
    {
        int c = tid & 63, half = tid >> 6;
#pragma unroll
        for (int rr = 0; rr < 3; rr++) {
            int row = half + rr * 2;
            int yy = y0 - 1 + row;
            bool rv = (unsigned)yy < 32u;
            const uint4* src = (const uint4*)(in + c * 1024 + yy * 32);
            uint4 q[4];
            if (rv) {
#pragma unroll
                for (int k2 = 0; k2 < 4; k2++) q[k2] = src[k2];
            } else {
#pragma unroll
                for (int k2 = 0; k2 < 4; k2++) q[k2] = make_uint4(0u, 0u, 0u, 0u);
            }
            const unsigned short* hv = (const unsigned short*)q;
            int rb = row * 34;
            Xs[rb * 72 + c] = 0;
            Xs[(rb + 33) * 72 + c] = 0;
#pragma unroll
            for (int x = 0; x < 32; x++) Xs[(rb + 1 + x) * 72 + c] = hv[x];
        }
    }
    __syncthreads();

    const uint4* wd = reinterpret_cast<const uint4*>(g_wd1);

#pragma unroll 1
    for (int p = 0; p < 4; p++) {
        int a = p >> 1, bp = p & 1;
        float D[2][4][4];
#pragma unroll
        for (int mt = 0; mt < 2; mt++)
#pragma unroll
            for (int nt = 0; nt < 4; nt++)
#pragma unroll
                for (int i = 0; i < 4; i++) D[mt][nt][i] = 0.f;

#pragma unroll
        for (int tt = 0; tt < 4; tt++) {
            int jy = tt >> 1, jx = tt & 1;
            int rowbase = ((nw + a + jy) * 34 + (bp + jx)) * 72;
#pragma unroll
            for (int kc = 0; kc < 4; kc++) {
                uint4 a0 = wd[((((p * 4 + tt) * 4 + kc) * 2 + 0) * 32) + lane];
                uint4 a1 = wd[((((p * 4 + tt) * 4 + kc) * 2 + 1) * 32) + lane];
                unsigned Bs[4][2];
#pragma unroll
                for (int nt = 0; nt < 4; nt++) {
                    int off = rowbase + (nt * 8 + g) * 72 + kc * 16 + 2 * tg;
                    Bs[nt][0] = *(const unsigned*)(Xs + off);
                    Bs[nt][1] = *(const unsigned*)(Xs + off + 8);
                }
#pragma unroll
                for (int nt = 0; nt < 4; nt++) {
                    mma_f16(D[0][nt], a0, Bs[nt]);
                    mma_f16(D[1][nt], a1, Bs[nt]);
                }
            }
        }

        int oy = 2 * (y0 + nw) + a;
#pragma unroll
        for (int mt = 0; mt < 2; mt++) {
#pragma unroll
            for (int ci2 = 0; ci2 < 2; ci2++) {
                int oc = mt * 16 + g + 8 * ci2;
                float bv = bias[oc];
#pragma unroll
                for (int nt = 0; nt < 4; nt++) {
#pragma unroll
                    for (int j = 0; j < 2; j++) {
                        float v = D[mt][nt][ci2 * 2 + j] + bv;
                        v = (v >= 0.f) ? v : 0.2f * v;
                        int ox = 2 * (nt * 8 + 2 * tg + j) + bp;
                        g_y1[(n * 32 + oc) * 4096 + oy * 64 + ox] = v;
                    }
                }
            }
        }
    }
}

// ---------------- encoder conv1: 1->16, 3x3 s2 p1, lrelu ----------------
__global__ __launch_bounds__(256) void enc_conv1(const float* __restrict__ x,
                                                 const float* __restrict__ w,
                                                 const float* __restrict__ bias) {
    __shared__ float sw[144], sb[16];
    int tid = threadIdx.x;
    if (tid < 144) sw[tid] = w[tid];
    if (tid < 16)  sb[tid] = bias[tid];
    __syncthreads();
    int n = blockIdx.x, p = blockIdx.y * 256 + tid;
    int oy = p >> 6, ox = p & 63;
    const float* xi = x + n * 16384;
    float win[9];
    int iy0 = 2 * oy - 1, ix0 = 2 * ox - 1;
#pragma unroll
    for (int ky = 0; ky < 3; ky++)
#pragma unroll
        for (int kx = 0; kx < 3; kx++) {
            int iy = iy0 + ky, ix = ix0 + kx;
            win[ky * 3 + kx] = ((unsigned)iy < 128u && (unsigned)ix < 128u) ? xi[iy * 128 + ix] : 0.f;
        }
#pragma unroll
    for (int oc = 0; oc < 16; oc++) {
        float a = sb[oc];
#pragma unroll
        for (int k = 0; k < 9; k++) a += sw[oc * 9 + k] * win[k];
        g_e1[(n * 16 + oc) * 4096 + p] = (a >= 0.f) ? a : 0.2f * a;
    }
}

// ---------------- encoder conv2: 16->64, 3x3 s2 p1, lrelu, emit fp16 ----------------
__global__ __launch_bounds__(256) void enc_conv2(const float* __restrict__ w,
                                                 const float* __restrict__ bias) {
    __shared__ float sw[9216];
    int tid = threadIdx.x;
    for (int i = tid; i < 9216; i += 256) sw[i] = w[i];
    __syncthreads();
    int n = blockIdx.x, p = blockIdx.y * 256 + tid;
    int oy = p >> 5, ox = p & 31;
    const float* in = g_e1 + n * 65536;
    float acc[64];
#pragma unroll
    for (int oc = 0; oc < 64; oc++) acc[oc] = bias[oc];
    int iy0 = 2 * oy - 1, ix0 = 2 * ox - 1;
#pragma unroll 1
    for (int ic = 0; ic < 16; ic++) {
        float win[9];
#pragma unroll
        for (int ky = 0; ky < 3; ky++)
#pragma unroll
            for (int kx = 0; kx < 3; kx++) {
                int iy = iy0 + ky, ix = ix0 + kx;
                win[ky * 3 + kx] = ((unsigned)iy < 64u && (unsigned)ix < 64u)
                                       ? in[ic * 4096 + iy * 64 + ix] : 0.f;
            }
#pragma unroll
        for (int oc = 0; oc < 64; oc++)
#pragma unroll
            for (int k = 0; k < 9; k++) acc[oc] += sw[(oc * 16 + ic) * 9 + k] * win[k];
    }
#pragma unroll
    for (int oc = 0; oc < 64; oc++) {
        float a = acc[oc];
        a = (a >= 0.f) ? a : 0.2f * a;
        g_e2p[(n * 64 + oc) * 1024 + p] = h16(a);
    }
}

// ---------------- deconv2: 32->1, 4x4 lhs_dil 2 pad 2, + transpose ----------------
__global__ __launch_bounds__(256) void deconv2(const float* __restrict__ w,
                                               const float* __restrict__ bias,
                                               float* __restrict__ out) {
    __shared__ float sw[512];
    int tid = threadIdx.x;
    for (int i = tid; i < 512; i += 256) sw[i] = w[i];
    __syncthreads();
    int n = blockIdx.x, p = blockIdx.y * 256 + tid;
    int oy = p >> 7, ox = p & 127;
    int ky0 = oy & 1, kx0 = ox & 1;
    int iyA = (oy + ky0 - 2) >> 1, iyB = iyA + 1;
    int ixA = (ox + kx0 - 2) >> 1, ixB = ixA + 1;
    bool yA = (unsigned)iyA < 64u, yB = (unsigned)iyB < 64u;
    bool xA = (unsigned)ixA < 64u, xB = (unsigned)ixB < 64u;
    const float* in = g_y1 + n * 131072;
    float acc = bias[0];
#pragma unroll 1
    for (int ic = 0; ic < 32; ic++) {
        const float* ip = in + ic * 4096;
        float vAA = (yA && xA) ? ip[iyA * 64 + ixA] : 0.f;
        float vAB = (yA && xB) ? ip[iyA * 64 + ixB] : 0.f;
        float vBA = (yB && xA) ? ip[iyB * 64 + ixA] : 0.f;
        float vBB = (yB && xB) ? ip[iyB * 64 + ixB] : 0.f;
        const float* wp = &sw[ic * 16];
        acc += wp[ky0 * 4 + kx0] * vAA + wp[ky0 * 4 + kx0 + 2] * vAB
             + wp[(ky0 + 2) * 4 + kx0] * vBA + wp[(ky0 + 2) * 4 + kx0 + 2] * vBB;
    }
    int t = n >> 5, b = n & 31;
    out[(b * 10 + t) * 16384 + p] = acc;
}

// ---------------- launch ----------------
extern "C" void kernel_launch(void* const* d_in, const int* in_sizes, int n_in,
                              void* d_out, int out_size) {
    const float* x           = (const float*)d_in[0];
    const float* enc_w1      = (const float*)d_in[1];
    const float* enc_b1      = (const float*)d_in[2];
    const float* enc_w2      = (const float*)d_in[3];
    const float* enc_b2      = (const float*)d_in[4];
    const float* enc_gru_wzr = (const float*)d_in[5];
    const float* enc_gru_bzr = (const float*)d_in[6];
    const float* enc_gru_wc  = (const float*)d_in[7];
    const float* enc_gru_bc  = (const float*)d_in[8];
    const float* dec_gru_wzr = (const float*)d_in[9];
    const float* dec_gru_bzr = (const float*)d_in[10];
    const float* dec_gru_wc  = (const float*)d_in[11];
    const float* dec_gru_bc  = (const float*)d_in[12];
    const float* dec_w1      = (const float*)d_in[13];
    const float* dec_b1      = (const float*)d_in[14];
    const float* dec_w2      = (const float*)d_in[15];
    const float* dec_b2      = (const float*)d_in[16];
    float* out = (float*)d_out;

    const int SMB = 288 * 72 * 2;   // 41472 B fp16 X tile
    cudaFuncSetAttribute(gru2, cudaFuncAttributeMaxDynamicSharedMemorySize, SMB);

    init_all<<<(2097152 + 921600 + 32768 + 255) / 256, 256>>>(
        enc_gru_wzr, enc_gru_wc, dec_gru_wzr, dec_gru_wc, dec_w1);              // #1
    enc_conv1<<<dim3(320, 16), 256>>>(x, enc_w1, enc_b1);                       // #2
    enc_conv2<<<dim3(320, 4), 256>>>(enc_w2, enc_b2);                           // #3

    // batched encoder x-part precompute (full-occupancy launches)
    gru2<<<dim3(320, 8, 2), 256, SMB>>>(0, 0, 8, 0,      enc_gru_bzr);          // #4 -> g_uzr
    gru2<<<dim3(320, 8, 1), 256, SMB>>>(0, 1, 4, 409600, enc_gru_bc);           // #5 -> g_uc

    for (int t = 0; t < 10; t++) {                                              // #6 = enc zr step (captured)
        gru2<<<dim3(32, 8, 2), 256, SMB>>>(t, 2, 8, 204800, enc_gru_bzr);
        gru2<<<dim3(32, 8, 1), 256, SMB>>>(t, 3, 4, 512000, enc_gru_bc);
    }
    for (int t = 0; t < 10; t++) {
        gru2<<<dim3(32, 8, 2), 256, SMB>>>(t, 4, 8, 614400, dec_gru_bzr);
        gru2<<<dim3(32, 8, 1), 256, SMB>>>(t, 5, 4, 819200, dec_gru_bc);
    }

    deconv1_tc<<<dim3(320, 8), 128>>>(dec_b1);
    deconv2<<<dim3(320, 64), 256>>>(dec_w2, dec_b2, out);
}

// round 13
// speedup vs baseline: 1.0751x; 1.0751x over previous
#include <cuda_runtime.h>
#include <cuda_fp16.h>
#include <stdint.h>
#include <math.h>

#define BB 32
#define TT 10

// ---------------- scratch (device globals; no allocs allowed) ----------------
__device__ float          g_e1 [320 * 16 * 64 * 64];   // encoder conv1 out (fp32)
__device__ unsigned short g_e2p[320 * 64 * 1024];      // encoder conv2 out (fp16 bits)
__device__ float          g_h  [BB * 64 * 1024];       // GRU hidden (fp32 master)
__device__ unsigned short g_hp [BB * 64 * 1024];       // h (fp16 bits)
__device__ float          g_z  [BB * 64 * 1024];       // z gate (fp32)
__device__ unsigned short g_rhp[BB * 64 * 1024];       // r*h (fp16 bits)
__device__ unsigned short g_hsp[TT * BB * 64 * 1024];  // decoder hidden outputs (fp16 bits)
__device__ float          g_y1 [320 * 32 * 64 * 64];   // deconv1 out (fp32)
__device__ __align__(16) unsigned short g_wp [921600]; // GRU W fragments, fp16
__device__ __align__(16) unsigned short g_wd1[32768];  // deconv1 W fragments, fp16

__device__ __forceinline__ unsigned short h16(float v) {
    return __half_as_ushort(__float2half(v));
}

// ---------------- fused init: zero h/hp + pack GRU weights + pack deconv1 weights ----------------
// GRU layout: [tap][kc][ob][lane][r][e] fp16
__global__ void init_all(const float* __restrict__ ewzr, const float* __restrict__ ewc,
                         const float* __restrict__ dwzr, const float* __restrict__ dwc,
                         const float* __restrict__ dw1) {
    long lidx = (long)blockIdx.x * 256 + threadIdx.x;
    if (lidx < 2097152) { g_h[lidx] = 0.f; g_hp[lidx] = 0; return; }
    int idx = (int)(lidx - 2097152);
    if (idx >= 921600) {
        // deconv1 weights: [p][tt][kc][ob][lane][r][e]
        int id = idx - 921600;
        if (id >= 32768) return;
        int e    = id & 1;
        int r    = (id >> 1) & 3;
        int lane = (id >> 3) & 31;
        int ob   = (id >> 8) & 1;
        int kc   = (id >> 9) & 3;
        int tt   = (id >> 11) & 3;
        int p    = (id >> 13) & 3;
        int g = lane >> 2, tg = lane & 3;
        int oc = ob * 16 + g + 8 * (r & 1);
        int ic = kc * 16 + 2 * tg + 8 * (r >> 1) + e;
        int a = p >> 1, bb = p & 1, jy = tt >> 1, jx = tt & 1;
        int kidx = (a + 2 * jy) * 4 + (bb + 2 * jx);
        g_wd1[id] = h16(dw1[(oc * 64 + ic) * 16 + kidx]);
        return;
    }
    const float* w; int OC, IC, icoff, dofs;
    if (idx < 409600)      { w = ewzr; OC = 128; IC = 128; icoff = 0;  dofs = 0; }
    else if (idx < 614400) { idx -= 409600; w = ewc;  OC = 64;  IC = 128; icoff = 0;  dofs = 409600; }
    else if (idx < 819200) { idx -= 614400; w = dwzr; OC = 128; IC = 64;  icoff = 64; dofs = 614400; }
    else                   { idx -= 819200; w = dwc;  OC = 64;  IC = 64;  icoff = 64; dofs = 819200; }
    int KC = IC >> 4, NOB = OC >> 4;
    int e    = idx & 1;
    int r    = (idx >> 1) & 3;
    int lane = (idx >> 3) & 31;
    int v    = idx >> 8;
    int ob   = v % NOB;
    int v2   = v / NOB;
    int kc   = v2 % KC;
    int tap  = v2 / KC;
    int g = lane >> 2, t = lane & 3;
    int oc = ob * 16 + g + 8 * (r & 1);
    int ic = kc * 16 + 2 * t + 8 * (r >> 1) + e;
    g_wp[dofs + idx] = h16(w[(oc * 128 + icoff + ic) * 25 + tap]);
}

// ---------------- mma helper (fp16 in, fp32 accum) ----------------
__device__ __forceinline__ void mma_f16(float (&d)[4], const uint4& a, const unsigned (&b)[2]) {
    asm volatile(
        "mma.sync.aligned.m16n8k16.row.col.f32.f16.f16.f32 "
        "{%0,%1,%2,%3}, {%4,%5,%6,%7}, {%8,%9}, {%0,%1,%2,%3};\n"
        : "+f"(d[0]), "+f"(d[1]), "+f"(d[2]), "+f"(d[3])
        : "r"(a.x), "r"(a.y), "r"(a.z), "r"(a.w), "r"(b[0]), "r"(b[1]));
}

// ---------------- GRU 5x5 conv via mma.sync fp16 (R10 structure); IC in 64-ch halves ----------------
// mode: 0=enc zr (e2p ++ hp)  1=enc cand (e2p ++ rhp)  2=dec zr (hp)  3=dec cand (rhp)
// act_mode 0: sigmoid -> r->g_rhp, z->g_z; act_mode 1: tanh -> h update (+g_hsp fp16)
template <int NH>
__global__ __launch_bounds__(256, 2) void gru2(int t, int mode, int nob, int wofs,
                                               const float* __restrict__ bias,
                                               int act_mode, int write_hs) {
    extern __shared__ unsigned short Xs[];   // [288 px][72] fp16 bits

    int b   = blockIdx.x;
    int y0  = blockIdx.y * 4;
    int och = blockIdx.z;
    int tid = threadIdx.x;
    int w   = tid >> 5, lane = tid & 31;
    int g   = lane >> 2, tg = lane & 3;
    int mw  = w >> 2, nw = w & 3;

    const unsigned short* s0p;
    const unsigned short* s1p;
    if (mode <= 1) {
        s0p = g_e2p + (b * 10 + t) * 65536;
        s1p = (mode == 0 ? g_hp : g_rhp) + b * 65536;
    } else {
        s0p = (mode == 2 ? g_hp : g_rhp) + b * 65536;
        s1p = s0p;
    }

    float D[2][4][4];
#pragma unroll
    for (int mt = 0; mt < 2; mt++)
#pragma unroll
        for (int nt = 0; nt < 4; nt++)
#pragma unroll
            for (int i = 0; i < 4; i++) D[mt][nt][i] = 0.f;

    const uint4* pw = reinterpret_cast<const uint4*>(g_wp) + (wofs >> 3);
    const int KC = NH * 4;
    const int S1 = nob * 32;
    const int S2 = (KC - 3) * nob * 32;
    const int ob0 = och * 4 + mw * 2;

#pragma unroll 1
    for (int h = 0; h < NH; h++) {
        if (h) __syncthreads();
        // ---- stage 64-ch half ----
        const unsigned short* base = (h == 0) ? s0p : s1p;
        int c = tid & 63;
#pragma unroll
        for (int it = 0; it < 2; it++) {
            int sy = (tid >> 6) | (it << 2);
            int yy = y0 - 2 + sy;
            bool rv = (unsigned)yy < 32u;
            const uint4* src = (const uint4*)(base + c * 1024 + yy * 32);
            uint4 q[4];
            if (rv) {
#pragma unroll
                for (int k2 = 0; k2 < 4; k2++) q[k2] = src[k2];
            } else {
#pragma unroll
                for (int k2 = 0; k2 < 4; k2++) q[k2] = make_uint4(0u, 0u, 0u, 0u);
            }
            const unsigned short* hv = (const unsigned short*)q;
            int rb = sy * 36;
#pragma unroll
            for (int sx = 0; sx < 36; sx++) {
                unsigned short v = (sx < 2 || sx >= 34) ? (unsigned short)0 : hv[sx - 2];
                Xs[(rb + sx) * 72 + c] = v;
            }
        }
        __syncthreads();

        // ---- MMA over taps x 4 kch (simple loop, A-prefetch only) ----
        int fb = (h * 4 * nob + ob0) * 32 + lane;
        uint4 ah[2];
#pragma unroll
        for (int mt = 0; mt < 2; mt++) ah[mt] = pw[fb + mt * 32];
#pragma unroll 1
        for (int tap = 0; tap < 25; tap++) {
            int dy = tap / 5, dx = tap - 5 * dy;
            int rowbase = ((nw + dy) * 36 + dx) * 72;
#pragma unroll
            for (int kch = 0; kch < 4; kch++) {
                int fn = (tap == 24 && kch == 3) ? fb : fb + (kch < 3 ? S1 : S2);
                uint4 nah[2];
#pragma unroll
                for (int mt = 0; mt < 2; mt++) nah[mt] = pw[fn + mt * 32];
                unsigned Bs[4][2];
#pragma unroll
                for (int nt = 0; nt < 4; nt++) {
                    int off = rowbase + (nt * 8 + g) * 72 + kch * 16 + 2 * tg;
                    Bs[nt][0] = *(const unsigned*)(Xs + off);
                    Bs[nt][1] = *(const unsigned*)(Xs + off + 8);
                }
#pragma unroll
                for (int mt = 0; mt < 2; mt++)
#pragma unroll
                    for (int nt = 0; nt < 4; nt++) mma_f16(D[mt][nt], ah[mt], Bs[nt]);
#pragma unroll
                for (int mt = 0; mt < 2; mt++) ah[mt] = nah[mt];
                fb = fn;
            }
        }
    }

    // ---- fused epilogue ----
    int y = y0 + nw;
#pragma unroll
    for (int mt = 0; mt < 2; mt++) {
#pragma unroll
        for (int ci2 = 0; ci2 < 2; ci2++) {
            int   ocG = och * 64 + mw * 32 + mt * 16 + g + 8 * ci2;
            float bv  = bias[ocG];
#pragma unroll
            for (int nt = 0; nt < 4; nt++) {
#pragma unroll
                for (int j = 0; j < 2; j++) {
                    float v  = D[mt][nt][ci2 * 2 + j] + bv;
                    int   x  = nt * 8 + 2 * tg + j;
                    int   px = y * 32 + x;
                    if (act_mode == 0) {
                        float s = 1.f / (1.f + expf(-v));
                        if (ocG < 64) {
                            int hi = (b * 64 + ocG) * 1024 + px;
                            g_rhp[hi] = h16(s * g_h[hi]);
                        } else {
                            g_z[(b * 64 + ocG - 64) * 1024 + px] = s;
                        }
                    } else {
                        float c  = tanhf(v);
                        int   hi = (b * 64 + ocG) * 1024 + px;
                        float z  = g_z[hi];
                        float hp = g_h[hi];
                        float hn = (1.f - z) * hp + z * c;
                        g_h[hi]  = hn;
                        g_hp[hi] = h16(hn);
                        if (write_hs) g_hsp[t * 2097152 + hi] = h16(hn);
                    }
                }
            }
        }
    }
}

// ---------------- deconv1 via mma.sync fp16: 64->32, 4x4 lhs_dil 2 pad 2, 4 parity 2x2 convs ----------------
__global__ __launch_bounds__(128) void deconv1_tc(const float* __restrict__ bias) {
    __shared__ unsigned short Xs[6 * 34 * 72];
    int n   = blockIdx.x;
    int y0  = blockIdx.y * 4;
    int tid = threadIdx.x;
    int w   = tid >> 5, lane = tid & 31;
    int g   = lane >> 2, tg = lane & 3;
    int nw  = w;

    const unsigned short* in = g_hsp + n * 65536;
    {
        int c = tid & 63, half = tid >> 6;
#pragma unroll
        for (int rr = 0; rr < 3; rr++) {
            int row = half + rr * 2;
            int yy = y0 - 1 + row;
            bool rv = (unsigned)yy < 32u;
            const uint4* src = (const uint4*)(in + c * 1024 + yy * 32);
            uint4 q[4];
            if (rv) {
#pragma unroll
                for (int k2 = 0; k2 < 4; k2++) q[k2] = src[k2];
            } else {
#pragma unroll
                for (int k2 = 0; k2 < 4; k2++) q[k2] = make_uint4(0u, 0u, 0u, 0u);
            }
            const unsigned short* hv = (const unsigned short*)q;
            int rb = row * 34;
            Xs[rb * 72 + c] = 0;
            Xs[(rb + 33) * 72 + c] = 0;
#pragma unroll
            for (int x = 0; x < 32; x++) Xs[(rb + 1 + x) * 72 + c] = hv[x];
        }
    }
    __syncthreads();

    const uint4* wd = reinterpret_cast<const uint4*>(g_wd1);

#pragma unroll 1
    for (int p = 0; p < 4; p++) {
        int a = p >> 1, bp = p & 1;
        float D[2][4][4];
#pragma unroll
        for (int mt = 0; mt < 2; mt++)
#pragma unroll
            for (int nt = 0; nt < 4; nt++)
#pragma unroll
                for (int i = 0; i < 4; i++) D[mt][nt][i] = 0.f;

#pragma unroll
        for (int tt = 0; tt < 4; tt++) {
            int jy = tt >> 1, jx = tt & 1;
            int rowbase = ((nw + a + jy) * 34 + (bp + jx)) * 72;
#pragma unroll
            for (int kc = 0; kc < 4; kc++) {
                uint4 a0 = wd[((((p * 4 + tt) * 4 + kc) * 2 + 0) * 32) + lane];
                uint4 a1 = wd[((((p * 4 + tt) * 4 + kc) * 2 + 1) * 32) + lane];
                unsigned Bs[4][2];
#pragma unroll
                for (int nt = 0; nt < 4; nt++) {
                    int off = rowbase + (nt * 8 + g) * 72 + kc * 16 + 2 * tg;
                    Bs[nt][0] = *(const unsigned*)(Xs + off);
                    Bs[nt][1] = *(const unsigned*)(Xs + off + 8);
                }
#pragma unroll
                for (int nt = 0; nt < 4; nt++) {
                    mma_f16(D[0][nt], a0, Bs[nt]);
                    mma_f16(D[1][nt], a1, Bs[nt]);
                }
            }
        }

        int oy = 2 * (y0 + nw) + a;
#pragma unroll
        for (int mt = 0; mt < 2; mt++) {
#pragma unroll
            for (int ci2 = 0; ci2 < 2; ci2++) {
                int oc = mt * 16 + g + 8 * ci2;
                float bv = bias[oc];
#pragma unroll
                for (int nt = 0; nt < 4; nt++) {
#pragma unroll
                    for (int j = 0; j < 2; j++) {
                        float v = D[mt][nt][ci2 * 2 + j] + bv;
                        v = (v >= 0.f) ? v : 0.2f * v;
                        int ox = 2 * (nt * 8 + 2 * tg + j) + bp;
                        g_y1[(n * 32 + oc) * 4096 + oy * 64 + ox] = v;
                    }
                }
            }
        }
    }
}

// ---------------- encoder conv1: 1->16, 3x3 s2 p1, lrelu ----------------
__global__ __launch_bounds__(256) void enc_conv1(const float* __restrict__ x,
                                                 const float* __restrict__ w,
                                                 const float* __restrict__ bias) {
    __shared__ float sw[144], sb[16];
    int tid = threadIdx.x;
    if (tid < 144) sw[tid] = w[tid];
    if (tid < 16)  sb[tid] = bias[tid];
    __syncthreads();
    int n = blockIdx.x, p = blockIdx.y * 256 + tid;
    int oy = p >> 6, ox = p & 63;
    const float* xi = x + n * 16384;
    float win[9];
    int iy0 = 2 * oy - 1, ix0 = 2 * ox - 1;
#pragma unroll
    for (int ky = 0; ky < 3; ky++)
#pragma unroll
        for (int kx = 0; kx < 3; kx++) {
            int iy = iy0 + ky, ix = ix0 + kx;
            win[ky * 3 + kx] = ((unsigned)iy < 128u && (unsigned)ix < 128u) ? xi[iy * 128 + ix] : 0.f;
        }
#pragma unroll
    for (int oc = 0; oc < 16; oc++) {
        float a = sb[oc];
#pragma unroll
        for (int k = 0; k < 9; k++) a += sw[oc * 9 + k] * win[k];
        g_e1[(n * 16 + oc) * 4096 + p] = (a >= 0.f) ? a : 0.2f * a;
    }
}

// ---------------- encoder conv2: 16->64, 3x3 s2 p1, lrelu, emit fp16 ----------------
__global__ __launch_bounds__(256) void enc_conv2(const float* __restrict__ w,
                                                 const float* __restrict__ bias) {
    __shared__ float sw[9216];
    int tid = threadIdx.x;
    for (int i = tid; i < 9216; i += 256) sw[i] = w[i];
    __syncthreads();
    int n = blockIdx.x, p = blockIdx.y * 256 + tid;
    int oy = p >> 5, ox = p & 31;
    const float* in = g_e1 + n * 65536;
    float acc[64];
#pragma unroll
    for (int oc = 0; oc < 64; oc++) acc[oc] = bias[oc];
    int iy0 = 2 * oy - 1, ix0 = 2 * ox - 1;
#pragma unroll 1
    for (int ic = 0; ic < 16; ic++) {
        float win[9];
#pragma unroll
        for (int ky = 0; ky < 3; ky++)
#pragma unroll
            for (int kx = 0; kx < 3; kx++) {
                int iy = iy0 + ky, ix = ix0 + kx;
                win[ky * 3 + kx] = ((unsigned)iy < 64u && (unsigned)ix < 64u)
                                       ? in[ic * 4096 + iy * 64 + ix] : 0.f;
            }
#pragma unroll
        for (int oc = 0; oc < 64; oc++)
#pragma unroll
            for (int k = 0; k < 9; k++) acc[oc] += sw[(oc * 16 + ic) * 9 + k] * win[k];
    }
#pragma unroll
    for (int oc = 0; oc < 64; oc++) {
        float a = acc[oc];
        a = (a >= 0.f) ? a : 0.2f * a;
        g_e2p[(n * 64 + oc) * 1024 + p] = h16(a);
    }
}

// ---------------- deconv2: 32->1, 4x4 lhs_dil 2 pad 2, + transpose ----------------
__global__ __launch_bounds__(256) void deconv2(const float* __restrict__ w,
                                               const float* __restrict__ bias,
                                               float* __restrict__ out) {
    __shared__ float sw[512];
    int tid = threadIdx.x;
    for (int i = tid; i < 512; i += 256) sw[i] = w[i];
    __syncthreads();
    int n = blockIdx.x, p = blockIdx.y * 256 + tid;
    int oy = p >> 7, ox = p & 127;
    int ky0 = oy & 1, kx0 = ox & 1;
    int iyA = (oy + ky0 - 2) >> 1, iyB = iyA + 1;
    int ixA = (ox + kx0 - 2) >> 1, ixB = ixA + 1;
    bool yA = (unsigned)iyA < 64u, yB = (unsigned)iyB < 64u;
    bool xA = (unsigned)ixA < 64u, xB = (unsigned)ixB < 64u;
    const float* in = g_y1 + n * 131072;
    float acc = bias[0];
#pragma unroll 1
    for (int ic = 0; ic < 32; ic++) {
        const float* ip = in + ic * 4096;
        float vAA = (yA && xA) ? ip[iyA * 64 + ixA] : 0.f;
        float vAB = (yA && xB) ? ip[iyA * 64 + ixB] : 0.f;
        float vBA = (yB && xA) ? ip[iyB * 64 + ixA] : 0.f;
        float vBB = (yB && xB) ? ip[iyB * 64 + ixB] : 0.f;
        const float* wp = &sw[ic * 16];
        acc += wp[ky0 * 4 + kx0] * vAA + wp[ky0 * 4 + kx0 + 2] * vAB
             + wp[(ky0 + 2) * 4 + kx0] * vBA + wp[(ky0 + 2) * 4 + kx0 + 2] * vBB;
    }
    int t = n >> 5, b = n & 31;
    out[(b * 10 + t) * 16384 + p] = acc;
}

// ---------------- launch ----------------
extern "C" void kernel_launch(void* const* d_in, const int* in_sizes, int n_in,
                              void* d_out, int out_size) {
    const float* x           = (const float*)d_in[0];
    const float* enc_w1      = (const float*)d_in[1];
    const float* enc_b1      = (const float*)d_in[2];
    const float* enc_w2      = (const float*)d_in[3];
    const float* enc_b2      = (const float*)d_in[4];
    const float* enc_gru_wzr = (const float*)d_in[5];
    const float* enc_gru_bzr = (const float*)d_in[6];
    const float* enc_gru_wc  = (const float*)d_in[7];
    const float* enc_gru_bc  = (const float*)d_in[8];
    const float* dec_gru_wzr = (const float*)d_in[9];
    const float* dec_gru_bzr = (const float*)d_in[10];
    const float* dec_gru_wc  = (const float*)d_in[11];
    const float* dec_gru_bc  = (const float*)d_in[12];
    const float* dec_w1      = (const float*)d_in[13];
    const float* dec_b1      = (const float*)d_in[14];
    const float* dec_w2      = (const float*)d_in[15];
    const float* dec_b2      = (const float*)d_in[16];
    float* out = (float*)d_out;

    const int SMB = 288 * 72 * 2;   // 41472 B fp16 X tile
    cudaFuncSetAttribute(gru2<2>, cudaFuncAttributeMaxDynamicSharedMemorySize, SMB);
    cudaFuncSetAttribute(gru2<1>, cudaFuncAttributeMaxDynamicSharedMemorySize, SMB);

    init_all<<<(2097152 + 921600 + 32768 + 255) / 256, 256>>>(
        enc_gru_wzr, enc_gru_wc, dec_gru_wzr, dec_gru_wc, dec_w1);            // #1
    enc_conv1<<<dim3(320, 16), 256>>>(x, enc_w1, enc_b1);                     // #2
    enc_conv2<<<dim3(320, 4), 256>>>(enc_w2, enc_b2);                         // #3

    for (int t = 0; t < 10; t++) {                                            // #4,#5,#6(captured)...
        gru2<2><<<dim3(32, 8, 2), 256, SMB>>>(t, 0, 8, 0, enc_gru_bzr, 0, 0);
        gru2<2><<<dim3(32, 8, 1), 256, SMB>>>(t, 1, 4, 409600, enc_gru_bc, 1, 0);
    }
    for (int t = 0; t < 10; t++) {
        gru2<1><<<dim3(32, 8, 2), 256, SMB>>>(t, 2, 8, 614400, dec_gru_bzr, 0, 0);
        gru2<1><<<dim3(32, 8, 1), 256, SMB>>>(t, 3, 4, 819200, dec_gru_bc, 1, 1);
    }

    deconv1_tc<<<dim3(320, 8), 128>>>(dec_b1);
    deconv2<<<dim3(320, 64), 256>>>(dec_w2, dec_b2, out);
}

// round 14
// speedup vs baseline: 1.0881x; 1.0122x over previous
#include <cuda_runtime.h>
#include <cuda_fp16.h>
#include <stdint.h>
#include <math.h>

#define BB 32
#define TT 10

// ---------------- scratch (device globals; no allocs allowed) ----------------
__device__ float          g_e1 [320 * 16 * 64 * 64];   // encoder conv1 out (fp32)
__device__ unsigned short g_e2p[320 * 64 * 1024];      // encoder conv2 out (fp16 bits)
__device__ float          g_h  [BB * 64 * 1024];       // GRU hidden (fp32 master)
__device__ unsigned short g_hp [BB * 64 * 1024];       // h (fp16 bits)
__device__ float          g_z  [BB * 64 * 1024];       // z gate (fp32)
__device__ unsigned short g_rhp[BB * 64 * 1024];       // r*h (fp16 bits)
__device__ unsigned short g_hsp[TT * BB * 64 * 1024];  // decoder hidden outputs (fp16 bits)
__device__ float          g_y1 [320 * 32 * 64 * 64];   // deconv1 out (fp32)
__device__ __align__(16) unsigned short g_wp [921600]; // GRU W fragments, fp16
__device__ __align__(16) unsigned short g_wd1[32768];  // deconv1 W fragments, fp16

__device__ __forceinline__ unsigned short h16(float v) {
    return __half_as_ushort(__float2half(v));
}

// ---------------- fused init: zero h/hp + pack GRU weights + pack deconv1 weights ----------------
// GRU layout: [tap][kc][ob][lane][r][e] fp16
__global__ void init_all(const float* __restrict__ ewzr, const float* __restrict__ ewc,
                         const float* __restrict__ dwzr, const float* __restrict__ dwc,
                         const float* __restrict__ dw1) {
    long lidx = (long)blockIdx.x * 256 + threadIdx.x;
    if (lidx < 2097152) { g_h[lidx] = 0.f; g_hp[lidx] = 0; return; }
    int idx = (int)(lidx - 2097152);
    if (idx >= 921600) {
        // deconv1 weights: [p][tt][kc][ob][lane][r][e]
        int id = idx - 921600;
        if (id >= 32768) return;
        int e    = id & 1;
        int r    = (id >> 1) & 3;
        int lane = (id >> 3) & 31;
        int ob   = (id >> 8) & 1;
        int kc   = (id >> 9) & 3;
        int tt   = (id >> 11) & 3;
        int p    = (id >> 13) & 3;
        int g = lane >> 2, tg = lane & 3;
        int oc = ob * 16 + g + 8 * (r & 1);
        int ic = kc * 16 + 2 * tg + 8 * (r >> 1) + e;
        int a = p >> 1, bb = p & 1, jy = tt >> 1, jx = tt & 1;
        int kidx = (a + 2 * jy) * 4 + (bb + 2 * jx);
        g_wd1[id] = h16(dw1[(oc * 64 + ic) * 16 + kidx]);
        return;
    }
    const float* w; int OC, IC, icoff, dofs;
    if (idx < 409600)      { w = ewzr; OC = 128; IC = 128; icoff = 0;  dofs = 0; }
    else if (idx < 614400) { idx -= 409600; w = ewc;  OC = 64;  IC = 128; icoff = 0;  dofs = 409600; }
    else if (idx < 819200) { idx -= 614400; w = dwzr; OC = 128; IC = 64;  icoff = 64; dofs = 614400; }
    else                   { idx -= 819200; w = dwc;  OC = 64;  IC = 64;  icoff = 64; dofs = 819200; }
    int KC = IC >> 4, NOB = OC >> 4;
    int e    = idx & 1;
    int r    = (idx >> 1) & 3;
    int lane = (idx >> 3) & 31;
    int v    = idx >> 8;
    int ob   = v % NOB;
    int v2   = v / NOB;
    int kc   = v2 % KC;
    int tap  = v2 / KC;
    int g = lane >> 2, t = lane & 3;
    int oc = ob * 16 + g + 8 * (r & 1);
    int ic = kc * 16 + 2 * t + 8 * (r >> 1) + e;
    g_wp[dofs + idx] = h16(w[(oc * 128 + icoff + ic) * 25 + tap]);
}

// ---------------- mma helper (fp16 in, fp32 accum) ----------------
__device__ __forceinline__ void mma_f16(float (&d)[4], const uint4& a, const unsigned (&b)[2]) {
    asm volatile(
        "mma.sync.aligned.m16n8k16.row.col.f32.f16.f16.f32 "
        "{%0,%1,%2,%3}, {%4,%5,%6,%7}, {%8,%9}, {%0,%1,%2,%3};\n"
        : "+f"(d[0]), "+f"(d[1]), "+f"(d[2]), "+f"(d[3])
        : "r"(a.x), "r"(a.y), "r"(a.z), "r"(a.w), "r"(b[0]), "r"(b[1]));
}

// ---------------- GRU 5x5 conv via mma.sync fp16; IC in 64-ch halves; pair-packed staging ----------------
// mode: 0=enc zr (e2p ++ hp)  1=enc cand (e2p ++ rhp)  2=dec zr (hp)  3=dec cand (rhp)
// act_mode 0: sigmoid -> r->g_rhp, z->g_z; act_mode 1: tanh -> h update (+g_hsp fp16)
template <int NH>
__global__ __launch_bounds__(256, 2) void gru2(int t, int mode, int nob, int wofs,
                                               const float* __restrict__ bias,
                                               int act_mode, int write_hs) {
    extern __shared__ unsigned short Xs[];   // [288 px][72] fp16 bits

    int b   = blockIdx.x;
    int y0  = blockIdx.y * 4;
    int och = blockIdx.z;
    int tid = threadIdx.x;
    int w   = tid >> 5, lane = tid & 31;
    int g   = lane >> 2, tg = lane & 3;
    int mw  = w >> 2, nw = w & 3;

    const unsigned short* s0p;
    const unsigned short* s1p;
    if (mode <= 1) {
        s0p = g_e2p + (b * 10 + t) * 65536;
        s1p = (mode == 0 ? g_hp : g_rhp) + b * 65536;
    } else {
        s0p = (mode == 2 ? g_hp : g_rhp) + b * 65536;
        s1p = s0p;
    }

    float D[2][4][4];
#pragma unroll
    for (int mt = 0; mt < 2; mt++)
#pragma unroll
        for (int nt = 0; nt < 4; nt++)
#pragma unroll
            for (int i = 0; i < 4; i++) D[mt][nt][i] = 0.f;

    const uint4* pw = reinterpret_cast<const uint4*>(g_wp) + (wofs >> 3);
    const int KC = NH * 4;
    const int S1 = nob * 32;
    const int S2 = (KC - 3) * nob * 32;
    const int ob0 = och * 4 + mw * 2;

#pragma unroll 1
    for (int h = 0; h < NH; h++) {
        if (h) __syncthreads();
        // ---- stage 64-ch half: channel-pair packed, one pass, STS.32 conflict-free ----
        {
            const unsigned short* base = (h == 0) ? s0p : s1p;
            int cp = tid & 31;               // channel pair 0..31 -> channels 2cp, 2cp+1
            int sy = tid >> 5;               // 0..7
            int yy = y0 - 2 + sy;
            bool rv = (unsigned)yy < 32u;
            const uint4* p0 = (const uint4*)(base + (2 * cp) * 1024 + yy * 32);
            const uint4* p1 = (const uint4*)(base + (2 * cp + 1) * 1024 + yy * 32);
            uint4 q0[4], q1[4];
            if (rv) {
#pragma unroll
                for (int k2 = 0; k2 < 4; k2++) { q0[k2] = p0[k2]; q1[k2] = p1[k2]; }
            } else {
#pragma unroll
                for (int k2 = 0; k2 < 4; k2++) {
                    q0[k2] = make_uint4(0u, 0u, 0u, 0u);
                    q1[k2] = make_uint4(0u, 0u, 0u, 0u);
                }
            }
            const unsigned short* h0 = (const unsigned short*)q0;
            const unsigned short* h1 = (const unsigned short*)q1;
            unsigned* Xw = (unsigned*)Xs;
            int rb = sy * 36;
#pragma unroll
            for (int sx = 0; sx < 36; sx++) {
                unsigned v = 0u;
                if (sx >= 2 && sx < 34) {
                    int x = sx - 2;
                    v = (unsigned)h0[x] | ((unsigned)h1[x] << 16);
                }
                Xw[(rb + sx) * 36 + cp] = v;
            }
        }
        __syncthreads();

        // ---- MMA over taps x 4 kch (simple loop, A-prefetch only) ----
        int fb = (h * 4 * nob + ob0) * 32 + lane;
        uint4 ah[2];
#pragma unroll
        for (int mt = 0; mt < 2; mt++) ah[mt] = pw[fb + mt * 32];
#pragma unroll 1
        for (int tap = 0; tap < 25; tap++) {
            int dy = tap / 5, dx = tap - 5 * dy;
            int rowbase = ((nw + dy) * 36 + dx) * 72;
#pragma unroll
            for (int kch = 0; kch < 4; kch++) {
                int fn = (tap == 24 && kch == 3) ? fb : fb + (kch < 3 ? S1 : S2);
                uint4 nah[2];
#pragma unroll
                for (int mt = 0; mt < 2; mt++) nah[mt] = pw[fn + mt * 32];
                unsigned Bs[4][2];
#pragma unroll
                for (int nt = 0; nt < 4; nt++) {
                    int off = rowbase + (nt * 8 + g) * 72 + kch * 16 + 2 * tg;
                    Bs[nt][0] = *(const unsigned*)(Xs + off);
                    Bs[nt][1] = *(const unsigned*)(Xs + off + 8);
                }
#pragma unroll
                for (int mt = 0; mt < 2; mt++)
#pragma unroll
                    for (int nt = 0; nt < 4; nt++) mma_f16(D[mt][nt], ah[mt], Bs[nt]);
#pragma unroll
                for (int mt = 0; mt < 2; mt++) ah[mt] = nah[mt];
                fb = fn;
            }
        }
    }

    // ---- fused epilogue ----
    int y = y0 + nw;
#pragma unroll
    for (int mt = 0; mt < 2; mt++) {
#pragma unroll
        for (int ci2 = 0; ci2 < 2; ci2++) {
            int   ocG = och * 64 + mw * 32 + mt * 16 + g + 8 * ci2;
            float bv  = bias[ocG];
#pragma unroll
            for (int nt = 0; nt < 4; nt++) {
#pragma unroll
                for (int j = 0; j < 2; j++) {
                    float v  = D[mt][nt][ci2 * 2 + j] + bv;
                    int   x  = nt * 8 + 2 * tg + j;
                    int   px = y * 32 + x;
                    if (act_mode == 0) {
                        float s = 1.f / (1.f + expf(-v));
                        if (ocG < 64) {
                            int hi = (b * 64 + ocG) * 1024 + px;
                            g_rhp[hi] = h16(s * g_h[hi]);
                        } else {
                            g_z[(b * 64 + ocG - 64) * 1024 + px] = s;
                        }
                    } else {
                        float c  = tanhf(v);
                        int   hi = (b * 64 + ocG) * 1024 + px;
                        float z  = g_z[hi];
                        float hp = g_h[hi];
                        float hn = (1.f - z) * hp + z * c;
                        g_h[hi]  = hn;
                        g_hp[hi] = h16(hn);
                        if (write_hs) g_hsp[t * 2097152 + hi] = h16(hn);
                    }
                }
            }
        }
    }
}

// ---------------- deconv1 via mma.sync fp16: 64->32, 4x4 lhs_dil 2 pad 2, 4 parity 2x2 convs ----------------
__global__ __launch_bounds__(128) void deconv1_tc(const float* __restrict__ bias) {
    __shared__ unsigned short Xs[6 * 34 * 72];
    int n   = blockIdx.x;
    int y0  = blockIdx.y * 4;
    int tid = threadIdx.x;
    int w   = tid >> 5, lane = tid & 31;
    int g   = lane >> 2, tg = lane & 3;
    int nw  = w;

    // ---- stage: channel-pair packed STS.32 ----
    const unsigned short* in = g_hsp + n * 65536;
    {
        int cp = tid & 31;
        int r0 = tid >> 5;                   // 0..3
        unsigned* Xw = (unsigned*)Xs;
#pragma unroll
        for (int rr = 0; rr < 2; rr++) {
            int row = r0 + rr * 4;
            if (row < 6) {
                int yy = y0 - 1 + row;
                bool rv = (unsigned)yy < 32u;
                const uint4* p0 = (const uint4*)(in + (2 * cp) * 1024 + yy * 32);
                const uint4* p1 = (const uint4*)(in + (2 * cp + 1) * 1024 + yy * 32);
                uint4 q0[4], q1[4];
                if (rv) {
#pragma unroll
                    for (int k2 = 0; k2 < 4; k2++) { q0[k2] = p0[k2]; q1[k2] = p1[k2]; }
                } else {
#pragma unroll
                    for (int k2 = 0; k2 < 4; k2++) {
                        q0[k2] = make_uint4(0u, 0u, 0u, 0u);
                        q1[k2] = make_uint4(0u, 0u, 0u, 0u);
                    }
                }
                const unsigned short* h0 = (const unsigned short*)q0;
                const unsigned short* h1 = (const unsigned short*)q1;
                int rb = row * 34;
                Xw[rb * 36 + cp] = 0u;
                Xw[(rb + 33) * 36 + cp] = 0u;
#pragma unroll
                for (int x = 0; x < 32; x++)
                    Xw[(rb + 1 + x) * 36 + cp] = (unsigned)h0[x] | ((unsigned)h1[x] << 16);
            }
        }
    }
    __syncthreads();

    const uint4* wd = reinterpret_cast<const uint4*>(g_wd1);

#pragma unroll 1
    for (int p = 0; p < 4; p++) {
        int a = p >> 1, bp = p & 1;
        float D[2][4][4];
#pragma unroll
        for (int mt = 0; mt < 2; mt++)
#pragma unroll
            for (int nt = 0; nt < 4; nt++)
#pragma unroll
                for (int i = 0; i < 4; i++) D[mt][nt][i] = 0.f;

#pragma unroll
        for (int tt = 0; tt < 4; tt++) {
            int jy = tt >> 1, jx = tt & 1;
            int rowbase = ((nw + a + jy) * 34 + (bp + jx)) * 72;
#pragma unroll
            for (int kc = 0; kc < 4; kc++) {
                uint4 a0 = wd[((((p * 4 + tt) * 4 + kc) * 2 + 0) * 32) + lane];
                uint4 a1 = wd[((((p * 4 + tt) * 4 + kc) * 2 + 1) * 32) + lane];
                unsigned Bs[4][2];
#pragma unroll
                for (int nt = 0; nt < 4; nt++) {
                    int off = rowbase + (nt * 8 + g) * 72 + kc * 16 + 2 * tg;
                    Bs[nt][0] = *(const unsigned*)(Xs + off);
                    Bs[nt][1] = *(const unsigned*)(Xs + off + 8);
                }
#pragma unroll
                for (int nt = 0; nt < 4; nt++) {
                    mma_f16(D[0][nt], a0, Bs[nt]);
                    mma_f16(D[1][nt], a1, Bs[nt]);
                }
            }
        }

        int oy = 2 * (y0 + nw) + a;
#pragma unroll
        for (int mt = 0; mt < 2; mt++) {
#pragma unroll
            for (int ci2 = 0; ci2 < 2; ci2++) {
                int oc = mt * 16 + g + 8 * ci2;
                float bv = bias[oc];
#pragma unroll
                for (int nt = 0; nt < 4; nt++) {
#pragma unroll
                    for (int j = 0; j < 2; j++) {
                        float v = D[mt][nt][ci2 * 2 + j] + bv;
                        v = (v >= 0.f) ? v : 0.2f * v;
                        int ox = 2 * (nt * 8 + 2 * tg + j) + bp;
                        g_y1[(n * 32 + oc) * 4096 + oy * 64 + ox] = v;
                    }
                }
            }
        }
    }
}

// ---------------- encoder conv1: 1->16, 3x3 s2 p1, lrelu ----------------
__global__ __launch_bounds__(256) void enc_conv1(const float* __restrict__ x,
                                                 const float* __restrict__ w,
                                                 const float* __restrict__ bias) {
    __shared__ float sw[144], sb[16];
    int tid = threadIdx.x;
    if (tid < 144) sw[tid] = w[tid];
    if (tid < 16)  sb[tid] = bias[tid];
    __syncthreads();
    int n = blockIdx.x, p = blockIdx.y * 256 + tid;
    int oy = p >> 6, ox = p & 63;
    const float* xi = x + n * 16384;
    float win[9];
    int iy0 = 2 * oy - 1, ix0 = 2 * ox - 1;
#pragma unroll
    for (int ky = 0; ky < 3; ky++)
#pragma unroll
        for (int kx = 0; kx < 3; kx++) {
            int iy = iy0 + ky, ix = ix0 + kx;
            win[ky * 3 + kx] = ((unsigned)iy < 128u && (unsigned)ix < 128u) ? xi[iy * 128 + ix] : 0.f;
        }
#pragma unroll
    for (int oc = 0; oc < 16; oc++) {
        float a = sb[oc];
#pragma unroll
        for (int k = 0; k < 9; k++) a += sw[oc * 9 + k] * win[k];
        g_e1[(n * 16 + oc) * 4096 + p] = (a >= 0.f) ? a : 0.2f * a;
    }
}

// ---------------- encoder conv2: 16->64, 3x3 s2 p1, lrelu, emit fp16 ----------------
__global__ __launch_bounds__(256) void enc_conv2(const float* __restrict__ w,
                                                 const float* __restrict__ bias) {
    __shared__ float sw[9216];
    int tid = threadIdx.x;
    for (int i = tid; i < 9216; i += 256) sw[i] = w[i];
    __syncthreads();
    int n = blockIdx.x, p = blockIdx.y * 256 + tid;
    int oy = p >> 5, ox = p & 31;
    const float* in = g_e1 + n * 65536;
    float acc[64];
#pragma unroll
    for (int oc = 0; oc < 64; oc++) acc[oc] = bias[oc];
    int iy0 = 2 * oy - 1, ix0 = 2 * ox - 1;
#pragma unroll 1
    for (int ic = 0; ic < 16; ic++) {
        float win[9];
#pragma unroll
        for (int ky = 0; ky < 3; ky++)
#pragma unroll
            for (int kx = 0; kx < 3; kx++) {
                int iy = iy0 + ky, ix = ix0 + kx;
                win[ky * 3 + kx] = ((unsigned)iy < 64u && (unsigned)ix < 64u)
                                       ? in[ic * 4096 + iy * 64 + ix] : 0.f;
            }
#pragma unroll
        for (int oc = 0; oc < 64; oc++)
#pragma unroll
            for (int k = 0; k < 9; k++) acc[oc] += sw[(oc * 16 + ic) * 9 + k] * win[k];
    }
#pragma unroll
    for (int oc = 0; oc < 64; oc++) {
        float a = acc[oc];
        a = (a >= 0.f) ? a : 0.2f * a;
        g_e2p[(n * 64 + oc) * 1024 + p] = h16(a);
    }
}

// ---------------- deconv2: 32->1, 4x4 lhs_dil 2 pad 2, + transpose ----------------
__global__ __launch_bounds__(256) void deconv2(const float* __restrict__ w,
                                               const float* __restrict__ bias,
                                               float* __restrict__ out) {
    __shared__ float sw[512];
    int tid = threadIdx.x;
    for (int i = tid; i < 512; i += 256) sw[i] = w[i];
    __syncthreads();
    int n = blockIdx.x, p = blockIdx.y * 256 + tid;
    int oy = p >> 7, ox = p & 127;
    int ky0 = oy & 1, kx0 = ox & 1;
    int iyA = (oy + ky0 - 2) >> 1, iyB = iyA + 1;
    int ixA = (ox + kx0 - 2) >> 1, ixB = ixA + 1;
    bool yA = (unsigned)iyA < 64u, yB = (unsigned)iyB < 64u;
    bool xA = (unsigned)ixA < 64u, xB = (unsigned)ixB < 64u;
    const float* in = g_y1 + n * 131072;
    float acc = bias[0];
#pragma unroll 1
    for (int ic = 0; ic < 32; ic++) {
        const float* ip = in + ic * 4096;
        float vAA = (yA && xA) ? ip[iyA * 64 + ixA] : 0.f;
        float vAB = (yA && xB) ? ip[iyA * 64 + ixB] : 0.f;
        float vBA = (yB && xA) ? ip[iyB * 64 + ixA] : 0.f;
        float vBB = (yB && xB) ? ip[iyB * 64 + ixB] : 0.f;
        const float* wp = &sw[ic * 16];
        acc += wp[ky0 * 4 + kx0] * vAA + wp[ky0 * 4 + kx0 + 2] * vAB
             + wp[(ky0 + 2) * 4 + kx0] * vBA + wp[(ky0 + 2) * 4 + kx0 + 2] * vBB;
    }
    int t = n >> 5, b = n & 31;
    out[(b * 10 + t) * 16384 + p] = acc;
}

// ---------------- launch ----------------
extern "C" void kernel_launch(void* const* d_in, const int* in_sizes, int n_in,
                              void* d_out, int out_size) {
    const float* x           = (const float*)d_in[0];
    const float* enc_w1      = (const float*)d_in[1];
    const float* enc_b1      = (const float*)d_in[2];
    const float* enc_w2      = (const float*)d_in[3];
    const float* enc_b2      = (const float*)d_in[4];
    const float* enc_gru_wzr = (const float*)d_in[5];
    const float* enc_gru_bzr = (const float*)d_in[6];
    const float* enc_gru_wc  = (const float*)d_in[7];
    const float* enc_gru_bc  = (const float*)d_in[8];
    const float* dec_gru_wzr = (const float*)d_in[9];
    const float* dec_gru_bzr = (const float*)d_in[10];
    const float* dec_gru_wc  = (const float*)d_in[11];
    const float* dec_gru_bc  = (const float*)d_in[12];
    const float* dec_w1      = (const float*)d_in[13];
    const float* dec_b1      = (const float*)d_in[14];
    const float* dec_w2      = (const float*)d_in[15];
    const float* dec_b2      = (const float*)d_in[16];
    float* out = (float*)d_out;

    const int SMB = 288 * 72 * 2;   // 41472 B fp16 X tile
    cudaFuncSetAttribute(gru2<2>, cudaFuncAttributeMaxDynamicSharedMemorySize, SMB);
    cudaFuncSetAttribute(gru2<1>, cudaFuncAttributeMaxDynamicSharedMemorySize, SMB);

    init_all<<<(2097152 + 921600 + 32768 + 255) / 256, 256>>>(
        enc_gru_wzr, enc_gru_wc, dec_gru_wzr, dec_gru_wc, dec_w1);            // #1
    enc_conv1<<<dim3(320, 16), 256>>>(x, enc_w1, enc_b1);                     // #2
    enc_conv2<<<dim3(320, 4), 256>>>(enc_w2, enc_b2);                         // #3

    for (int t = 0; t < 10; t++) {                                            // #4,#5,#6(captured)...
        gru2<2><<<dim3(32, 8, 2), 256, SMB>>>(t, 0, 8, 0, enc_gru_bzr, 0, 0);
        gru2<2><<<dim3(32, 8, 1), 256, SMB>>>(t, 1, 4, 409600, enc_gru_bc, 1, 0);
    }
    for (int t = 0; t < 10; t++) {
        gru2<1><<<dim3(32, 8, 2), 256, SMB>>>(t, 2, 8, 614400, dec_gru_bzr, 0, 0);
        gru2<1><<<dim3(32, 8, 1), 256, SMB>>>(t, 3, 4, 819200, dec_gru_bc, 1, 1);
    }

    deconv1_tc<<<dim3(320, 8), 128>>>(dec_b1);
    deconv2<<<dim3(320, 64), 256>>>(dec_w2, dec_b2, out);
}

// round 15
// speedup vs baseline: 1.0892x; 1.0010x over previous
#include <cuda_runtime.h>
#include <cuda_fp16.h>
#include <stdint.h>
#include <math.h>

#define BB 32
#define TT 10

// ---------------- scratch (device globals; no allocs allowed) ----------------
__device__ float          g_e1 [320 * 16 * 64 * 64];   // encoder conv1 out (fp32)
__device__ unsigned short g_e2p[320 * 64 * 1024];      // encoder conv2 out (fp16 bits)
__device__ float          g_h  [BB * 64 * 1024];       // GRU hidden (fp32 master)
__device__ unsigned short g_hp [BB * 64 * 1024];       // h (fp16 bits)
__device__ float          g_z  [BB * 64 * 1024];       // z gate (fp32)
__device__ unsigned short g_rhp[BB * 64 * 1024];       // r*h (fp16 bits)
__device__ unsigned short g_hsp[TT * BB * 64 * 1024];  // decoder hidden outputs (fp16 bits)
__device__ float          g_y1 [320 * 32 * 64 * 64];   // deconv1 out (fp32)
__device__ __align__(16) unsigned short g_wp [921600]; // GRU W fragments, fp16
__device__ __align__(16) unsigned short g_wd1[32768];  // deconv1 W fragments, fp16

__device__ __forceinline__ unsigned short h16(float v) {
    return __half_as_ushort(__float2half(v));
}

// ---------------- fused init: zero h/hp + pack GRU weights + pack deconv1 weights ----------------
// GRU layout: [tap][kc][ob][lane][r][e] fp16
__global__ void init_all(const float* __restrict__ ewzr, const float* __restrict__ ewc,
                         const float* __restrict__ dwzr, const float* __restrict__ dwc,
                         const float* __restrict__ dw1) {
    long lidx = (long)blockIdx.x * 256 + threadIdx.x;
    if (lidx < 2097152) { g_h[lidx] = 0.f; g_hp[lidx] = 0; return; }
    int idx = (int)(lidx - 2097152);
    if (idx >= 921600) {
        // deconv1 weights: [p][tt][kc][ob][lane][r][e]
        int id = idx - 921600;
        if (id >= 32768) return;
        int e    = id & 1;
        int r    = (id >> 1) & 3;
        int lane = (id >> 3) & 31;
        int ob   = (id >> 8) & 1;
        int kc   = (id >> 9) & 3;
        int tt   = (id >> 11) & 3;
        int p    = (id >> 13) & 3;
        int g = lane >> 2, tg = lane & 3;
        int oc = ob * 16 + g + 8 * (r & 1);
        int ic = kc * 16 + 2 * tg + 8 * (r >> 1) + e;
        int a = p >> 1, bb = p & 1, jy = tt >> 1, jx = tt & 1;
        int kidx = (a + 2 * jy) * 4 + (bb + 2 * jx);
        g_wd1[id] = h16(dw1[(oc * 64 + ic) * 16 + kidx]);
        return;
    }
    const float* w; int OC, IC, icoff, dofs;
    if (idx < 409600)      { w = ewzr; OC = 128; IC = 128; icoff = 0;  dofs = 0; }
    else if (idx < 614400) { idx -= 409600; w = ewc;  OC = 64;  IC = 128; icoff = 0;  dofs = 409600; }
    else if (idx < 819200) { idx -= 614400; w = dwzr; OC = 128; IC = 64;  icoff = 64; dofs = 614400; }
    else                   { idx -= 819200; w = dwc;  OC = 64;  IC = 64;  icoff = 64; dofs = 819200; }
    int KC = IC >> 4, NOB = OC >> 4;
    int e    = idx & 1;
    int r    = (idx >> 1) & 3;
    int lane = (idx >> 3) & 31;
    int v    = idx >> 8;
    int ob   = v % NOB;
    int v2   = v / NOB;
    int kc   = v2 % KC;
    int tap  = v2 / KC;
    int g = lane >> 2, t = lane & 3;
    int oc = ob * 16 + g + 8 * (r & 1);
    int ic = kc * 16 + 2 * t + 8 * (r >> 1) + e;
    g_wp[dofs + idx] = h16(w[(oc * 128 + icoff + ic) * 25 + tap]);
}

// ---------------- mma helper (fp16 in, fp32 accum) ----------------
__device__ __forceinline__ void mma_f16(float (&d)[4], const uint4& a, const unsigned (&b)[2]) {
    asm volatile(
        "mma.sync.aligned.m16n8k16.row.col.f32.f16.f16.f32 "
        "{%0,%1,%2,%3}, {%4,%5,%6,%7}, {%8,%9}, {%0,%1,%2,%3};\n"
        : "+f"(d[0]), "+f"(d[1]), "+f"(d[2]), "+f"(d[3])
        : "r"(a.x), "r"(a.y), "r"(a.z), "r"(a.w), "r"(b[0]), "r"(b[1]));
}

// ---------------- GRU 5x5 conv via mma.sync fp16; IC in 64-ch halves; warp tile MT x 4 ----------------
// mode: 0=enc zr (e2p ++ hp)  1=enc cand (e2p ++ rhp)  2=dec zr (hp)  3=dec cand (rhp)
// act_mode 0: sigmoid -> r->g_rhp, z->g_z; act_mode 1: tanh -> h update (+g_hsp fp16)
// MT=4: CTA covers all 128 OC (zr kernels, single-wave grid). MT=2: 64 OC (cand kernels).
template <int NH, int MT>
__global__ __launch_bounds__(256, 2) void gru2(int t, int mode, int nob, int wofs,
                                               const float* __restrict__ bias,
                                               int act_mode, int write_hs) {
    extern __shared__ unsigned short Xs[];   // [288 px][72] fp16 bits

    int b   = blockIdx.x;
    int y0  = blockIdx.y * 4;
    int tid = threadIdx.x;
    int w   = tid >> 5, lane = tid & 31;
    int g   = lane >> 2, tg = lane & 3;
    int mw  = w >> 2, nw = w & 3;

    const unsigned short* s0p;
    const unsigned short* s1p;
    if (mode <= 1) {
        s0p = g_e2p + (b * 10 + t) * 65536;
        s1p = (mode == 0 ? g_hp : g_rhp) + b * 65536;
    } else {
        s0p = (mode == 2 ? g_hp : g_rhp) + b * 65536;
        s1p = s0p;
    }

    float D[MT][4][4];
#pragma unroll
    for (int mt = 0; mt < MT; mt++)
#pragma unroll
        for (int nt = 0; nt < 4; nt++)
#pragma unroll
            for (int i = 0; i < 4; i++) D[mt][nt][i] = 0.f;

    const uint4* pw = reinterpret_cast<const uint4*>(g_wp) + (wofs >> 3);
    const int KC = NH * 4;
    const int S1 = nob * 32;
    const int S2 = (KC - 3) * nob * 32;
    const int ob0 = mw * MT;                 // MT=4: mw covers 4 ob; MT=2: 2 ob (nob=4)

#pragma unroll 1
    for (int h = 0; h < NH; h++) {
        if (h) __syncthreads();
        // ---- stage 64-ch half: channel-pair packed, one pass, STS.32 conflict-free ----
        {
            const unsigned short* base = (h == 0) ? s0p : s1p;
            int cp = tid & 31;               // channel pair 0..31 -> channels 2cp, 2cp+1
            int sy = tid >> 5;               // 0..7
            int yy = y0 - 2 + sy;
            bool rv = (unsigned)yy < 32u;
            const uint4* p0 = (const uint4*)(base + (2 * cp) * 1024 + yy * 32);
            const uint4* p1 = (const uint4*)(base + (2 * cp + 1) * 1024 + yy * 32);
            uint4 q0[4], q1[4];
            if (rv) {
#pragma unroll
                for (int k2 = 0; k2 < 4; k2++) { q0[k2] = p0[k2]; q1[k2] = p1[k2]; }
            } else {
#pragma unroll
                for (int k2 = 0; k2 < 4; k2++) {
                    q0[k2] = make_uint4(0u, 0u, 0u, 0u);
                    q1[k2] = make_uint4(0u, 0u, 0u, 0u);
                }
            }
            const unsigned short* h0 = (const unsigned short*)q0;
            const unsigned short* h1 = (const unsigned short*)q1;
            unsigned* Xw = (unsigned*)Xs;
            int rb = sy * 36;
#pragma unroll
            for (int sx = 0; sx < 36; sx++) {
                unsigned v = 0u;
                if (sx >= 2 && sx < 34) {
                    int x = sx - 2;
                    v = (unsigned)h0[x] | ((unsigned)h1[x] << 16);
                }
                Xw[(rb + sx) * 36 + cp] = v;
            }
        }
        __syncthreads();

        // ---- MMA over taps x 4 kch (A-prefetch only) ----
        int fb = (h * 4 * nob + ob0) * 32 + lane;
        uint4 ah[MT];
#pragma unroll
        for (int mt = 0; mt < MT; mt++) ah[mt] = pw[fb + mt * 32];
#pragma unroll 1
        for (int tap = 0; tap < 25; tap++) {
            int dy = tap / 5, dx = tap - 5 * dy;
            int rowbase = ((nw + dy) * 36 + dx) * 72;
#pragma unroll
            for (int kch = 0; kch < 4; kch++) {
                int fn = (tap == 24 && kch == 3) ? fb : fb + (kch < 3 ? S1 : S2);
                uint4 nah[MT];
#pragma unroll
                for (int mt = 0; mt < MT; mt++) nah[mt] = pw[fn + mt * 32];
                unsigned Bs[4][2];
#pragma unroll
                for (int nt = 0; nt < 4; nt++) {
                    int off = rowbase + (nt * 8 + g) * 72 + kch * 16 + 2 * tg;
                    Bs[nt][0] = *(const unsigned*)(Xs + off);
                    Bs[nt][1] = *(const unsigned*)(Xs + off + 8);
                }
#pragma unroll
                for (int mt = 0; mt < MT; mt++)
#pragma unroll
                    for (int nt = 0; nt < 4; nt++) mma_f16(D[mt][nt], ah[mt], Bs[nt]);
#pragma unroll
                for (int mt = 0; mt < MT; mt++) ah[mt] = nah[mt];
                fb = fn;
            }
        }
    }

    // ---- fused epilogue ----
    int y = y0 + nw;
#pragma unroll
    for (int mt = 0; mt < MT; mt++) {
#pragma unroll
        for (int ci2 = 0; ci2 < 2; ci2++) {
            int   ocG = (ob0 + mt) * 16 + g + 8 * ci2;
            float bv  = bias[ocG];
#pragma unroll
            for (int nt = 0; nt < 4; nt++) {
#pragma unroll
                for (int j = 0; j < 2; j++) {
                    float v  = D[mt][nt][ci2 * 2 + j] + bv;
                    int   x  = nt * 8 + 2 * tg + j;
                    int   px = y * 32 + x;
                    if (act_mode == 0) {
                        float s = 1.f / (1.f + expf(-v));
                        if (ocG < 64) {
                            int hi = (b * 64 + ocG) * 1024 + px;
                            g_rhp[hi] = h16(s * g_h[hi]);
                        } else {
                            g_z[(b * 64 + ocG - 64) * 1024 + px] = s;
                        }
                    } else {
                        float c  = tanhf(v);
                        int   hi = (b * 64 + ocG) * 1024 + px;
                        float z  = g_z[hi];
                        float hp = g_h[hi];
                        float hn = (1.f - z) * hp + z * c;
                        g_h[hi]  = hn;
                        g_hp[hi] = h16(hn);
                        if (write_hs) g_hsp[t * 2097152 + hi] = h16(hn);
                    }
                }
            }
        }
    }
}

// ---------------- deconv1 via mma.sync fp16: 64->32, 4x4 lhs_dil 2 pad 2, 4 parity 2x2 convs ----------------
__global__ __launch_bounds__(128) void deconv1_tc(const float* __restrict__ bias) {
    __shared__ unsigned short Xs[6 * 34 * 72];
    int n   = blockIdx.x;
    int y0  = blockIdx.y * 4;
    int tid = threadIdx.x;
    int w   = tid >> 5, lane = tid & 31;
    int g   = lane >> 2, tg = lane & 3;
    int nw  = w;

    // ---- stage: channel-pair packed STS.32 ----
    const unsigned short* in = g_hsp + n * 65536;
    {
        int cp = tid & 31;
        int r0 = tid >> 5;                   // 0..3
        unsigned* Xw = (unsigned*)Xs;
#pragma unroll
        for (int rr = 0; rr < 2; rr++) {
            int row = r0 + rr * 4;
            if (row < 6) {
                int yy = y0 - 1 + row;
                bool rv = (unsigned)yy < 32u;
                const uint4* p0 = (const uint4*)(in + (2 * cp) * 1024 + yy * 32);
                const uint4* p1 = (const uint4*)(in + (2 * cp + 1) * 1024 + yy * 32);
                uint4 q0[4], q1[4];
                if (rv) {
#pragma unroll
                    for (int k2 = 0; k2 < 4; k2++) { q0[k2] = p0[k2]; q1[k2] = p1[k2]; }
                } else {
#pragma unroll
                    for (int k2 = 0; k2 < 4; k2++) {
                        q0[k2] = make_uint4(0u, 0u, 0u, 0u);
                        q1[k2] = make_uint4(0u, 0u, 0u, 0u);
                    }
                }
                const unsigned short* h0 = (const unsigned short*)q0;
                const unsigned short* h1 = (const unsigned short*)q1;
                int rb = row * 34;
                Xw[rb * 36 + cp] = 0u;
                Xw[(rb + 33) * 36 + cp] = 0u;
#pragma unroll
                for (int x = 0; x < 32; x++)
                    Xw[(rb + 1 + x) * 36 + cp] = (unsigned)h0[x] | ((unsigned)h1[x] << 16);
            }
        }
    }
    __syncthreads();

    const uint4* wd = reinterpret_cast<const uint4*>(g_wd1);

#pragma unroll 1
    for (int p = 0; p < 4; p++) {
        int a = p >> 1, bp = p & 1;
        float D[2][4][4];
#pragma unroll
        for (int mt = 0; mt < 2; mt++)
#pragma unroll
            for (int nt = 0; nt < 4; nt++)
#pragma unroll
                for (int i = 0; i < 4; i++) D[mt][nt][i] = 0.f;

#pragma unroll
        for (int tt = 0; tt < 4; tt++) {
            int jy = tt >> 1, jx = tt & 1;
            int rowbase = ((nw + a + jy) * 34 + (bp + jx)) * 72;
#pragma unroll
            for (int kc = 0; kc < 4; kc++) {
                uint4 a0 = wd[((((p * 4 + tt) * 4 + kc) * 2 + 0) * 32) + lane];
                uint4 a1 = wd[((((p * 4 + tt) * 4 + kc) * 2 + 1) * 32) + lane];
                unsigned Bs[4][2];
#pragma unroll
                for (int nt = 0; nt < 4; nt++) {
                    int off = rowbase + (nt * 8 + g) * 72 + kc * 16 + 2 * tg;
                    Bs[nt][0] = *(const unsigned*)(Xs + off);
                    Bs[nt][1] = *(const unsigned*)(Xs + off + 8);
                }
#pragma unroll
                for (int nt = 0; nt < 4; nt++) {
                    mma_f16(D[0][nt], a0, Bs[nt]);
                    mma_f16(D[1][nt], a1, Bs[nt]);
                }
            }
        }

        int oy = 2 * (y0 + nw) + a;
#pragma unroll
        for (int mt = 0; mt < 2; mt++) {
#pragma unroll
            for (int ci2 = 0; ci2 < 2; ci2++) {
                int oc = mt * 16 + g + 8 * ci2;
                float bv = bias[oc];
#pragma unroll
                for (int nt = 0; nt < 4; nt++) {
#pragma unroll
                    for (int j = 0; j < 2; j++) {
                        float v = D[mt][nt][ci2 * 2 + j] + bv;
                        v = (v >= 0.f) ? v : 0.2f * v;
                        int ox = 2 * (nt * 8 + 2 * tg + j) + bp;
                        g_y1[(n * 32 + oc) * 4096 + oy * 64 + ox] = v;
                    }
                }
            }
        }
    }
}

// ---------------- encoder conv1: 1->16, 3x3 s2 p1, lrelu ----------------
__global__ __launch_bounds__(256) void enc_conv1(const float* __restrict__ x,
                                                 const float* __restrict__ w,
                                                 const float* __restrict__ bias) {
    __shared__ float sw[144], sb[16];
    int tid = threadIdx.x;
    if (tid < 144) sw[tid] = w[tid];
    if (tid < 16)  sb[tid] = bias[tid];
    __syncthreads();
    int n = blockIdx.x, p = blockIdx.y * 256 + tid;
    int oy = p >> 6, ox = p & 63;
    const float* xi = x + n * 16384;
    float win[9];
    int iy0 = 2 * oy - 1, ix0 = 2 * ox - 1;
#pragma unroll
    for (int ky = 0; ky < 3; ky++)
#pragma unroll
        for (int kx = 0; kx < 3; kx++) {
            int iy = iy0 + ky, ix = ix0 + kx;
            win[ky * 3 + kx] = ((unsigned)iy < 128u && (unsigned)ix < 128u) ? xi[iy * 128 + ix] : 0.f;
        }
#pragma unroll
    for (int oc = 0; oc < 16; oc++) {
        float a = sb[oc];
#pragma unroll
        for (int k = 0; k < 9; k++) a += sw[oc * 9 + k] * win[k];
        g_e1[(n * 16 + oc) * 4096 + p] = (a >= 0.f) ? a : 0.2f * a;
    }
}

// ---------------- encoder conv2: 16->64, 3x3 s2 p1, lrelu, emit fp16 ----------------
__global__ __launch_bounds__(256) void enc_conv2(const float* __restrict__ w,
                                                 const float* __restrict__ bias) {
    __shared__ float sw[9216];
    int tid = threadIdx.x;
    for (int i = tid; i < 9216; i += 256) sw[i] = w[i];
    __syncthreads();
    int n = blockIdx.x, p = blockIdx.y * 256 + tid;
    int oy = p >> 5, ox = p & 31;
    const float* in = g_e1 + n * 65536;
    float acc[64];
#pragma unroll
    for (int oc = 0; oc < 64; oc++) acc[oc] = bias[oc];
    int iy0 = 2 * oy - 1, ix0 = 2 * ox - 1;
#pragma unroll 1
    for (int ic = 0; ic < 16; ic++) {
        float win[9];
#pragma unroll
        for (int ky = 0; ky < 3; ky++)
#pragma unroll
            for (int kx = 0; kx < 3; kx++) {
                int iy = iy0 + ky, ix = ix0 + kx;
                win[ky * 3 + kx] = ((unsigned)iy < 64u && (unsigned)ix < 64u)
                                       ? in[ic * 4096 + iy * 64 + ix] : 0.f;
            }
#pragma unroll
        for (int oc = 0; oc < 64; oc++)
#pragma unroll
            for (int k = 0; k < 9; k++) acc[oc] += sw[(oc * 16 + ic) * 9 + k] * win[k];
    }
#pragma unroll
    for (int oc = 0; oc < 64; oc++) {
        float a = acc[oc];
        a = (a >= 0.f) ? a : 0.2f * a;
        g_e2p[(n * 64 + oc) * 1024 + p] = h16(a);
    }
}

// ---------------- deconv2: 32->1, 4x4 lhs_dil 2 pad 2, + transpose ----------------
__global__ __launch_bounds__(256) void deconv2(const float* __restrict__ w,
                                               const float* __restrict__ bias,
                                               float* __restrict__ out) {
    __shared__ float sw[512];
    int tid = threadIdx.x;
    for (int i = tid; i < 512; i += 256) sw[i] = w[i];
    __syncthreads();
    int n = blockIdx.x, p = blockIdx.y * 256 + tid;
    int oy = p >> 7, ox = p & 127;
    int ky0 = oy & 1, kx0 = ox & 1;
    int iyA = (oy + ky0 - 2) >> 1, iyB = iyA + 1;
    int ixA = (ox + kx0 - 2) >> 1, ixB = ixA + 1;
    bool yA = (unsigned)iyA < 64u, yB = (unsigned)iyB < 64u;
    bool xA = (unsigned)ixA < 64u, xB = (unsigned)ixB < 64u;
    const float* in = g_y1 + n * 131072;
    float acc = bias[0];
#pragma unroll 1
    for (int ic = 0; ic < 32; ic++) {
        const float* ip = in + ic * 4096;
        float vAA = (yA && xA) ? ip[iyA * 64 + ixA] : 0.f;
        float vAB = (yA && xB) ? ip[iyA * 64 + ixB] : 0.f;
        float vBA = (yB && xA) ? ip[iyB * 64 + ixA] : 0.f;
        float vBB = (yB && xB) ? ip[iyB * 64 + ixB] : 0.f;
        const float* wp = &sw[ic * 16];
        acc += wp[ky0 * 4 + kx0] * vAA + wp[ky0 * 4 + kx0 + 2] * vAB
             + wp[(ky0 + 2) * 4 + kx0] * vBA + wp[(ky0 + 2) * 4 + kx0 + 2] * vBB;
    }
    int t = n >> 5, b = n & 31;
    out[(b * 10 + t) * 16384 + p] = acc;
}

// ---------------- launch ----------------
extern "C" void kernel_launch(void* const* d_in, const int* in_sizes, int n_in,
                              void* d_out, int out_size) {
    const float* x           = (const float*)d_in[0];
    const float* enc_w1      = (const float*)d_in[1];
    const float* enc_b1      = (const float*)d_in[2];
    const float* enc_w2      = (const float*)d_in[3];
    const float* enc_b2      = (const float*)d_in[4];
    const float* enc_gru_wzr = (const float*)d_in[5];
    const float* enc_gru_bzr = (const float*)d_in[6];
    const float* enc_gru_wc  = (const float*)d_in[7];
    const float* enc_gru_bc  = (const float*)d_in[8];
    const float* dec_gru_wzr = (const float*)d_in[9];
    const float* dec_gru_bzr = (const float*)d_in[10];
    const float* dec_gru_wc  = (const float*)d_in[11];
    const float* dec_gru_bc  = (const float*)d_in[12];
    const float* dec_w1      = (const float*)d_in[13];
    const float* dec_b1      = (const float*)d_in[14];
    const float* dec_w2      = (const float*)d_in[15];
    const float* dec_b2      = (const float*)d_in[16];
    float* out = (float*)d_out;

    const int SMB = 288 * 72 * 2;   // 41472 B fp16 X tile
    cudaFuncSetAttribute((gru2<2, 4>), cudaFuncAttributeMaxDynamicSharedMemorySize, SMB);
    cudaFuncSetAttribute((gru2<2, 2>), cudaFuncAttributeMaxDynamicSharedMemorySize, SMB);
    cudaFuncSetAttribute((gru2<1, 4>), cudaFuncAttributeMaxDynamicSharedMemorySize, SMB);
    cudaFuncSetAttribute((gru2<1, 2>), cudaFuncAttributeMaxDynamicSharedMemorySize, SMB);

    init_all<<<(2097152 + 921600 + 32768 + 255) / 256, 256>>>(
        enc_gru_wzr, enc_gru_wc, dec_gru_wzr, dec_gru_wc, dec_w1);            // #1
    enc_conv1<<<dim3(320, 16), 256>>>(x, enc_w1, enc_b1);                     // #2
    enc_conv2<<<dim3(320, 4), 256>>>(enc_w2, enc_b2);                         // #3

    for (int t = 0; t < 10; t++) {                                            // #4,#5,#6(captured)...
        gru2<2, 4><<<dim3(32, 8), 256, SMB>>>(t, 0, 8, 0, enc_gru_bzr, 0, 0);
        gru2<2, 2><<<dim3(32, 8), 256, SMB>>>(t, 1, 4, 409600, enc_gru_bc, 1, 0);
    }
    for (int t = 0; t < 10; t++) {
        gru2<1, 4><<<dim3(32, 8), 256, SMB>>>(t, 2, 8, 614400, dec_gru_bzr, 0, 0);
        gru2<1, 2><<<dim3(32, 8), 256, SMB>>>(t, 3, 4, 819200, dec_gru_bc, 1, 1);
    }

    deconv1_tc<<<dim3(320, 8), 128>>>(dec_b1);
    deconv2<<<dim3(320, 64), 256>>>(dec_w2, dec_b2, out);
}

// round 16
// speedup vs baseline: 1.2133x; 1.1139x over previous
#include <cuda_runtime.h>
#include <cuda_fp16.h>
#include <stdint.h>
#include <math.h>

#define BB 32
#define TT 10

// ---------------- scratch (device globals; no allocs allowed) ----------------
__device__ unsigned short g_e1p[320 * 16 * 64 * 64];   // encoder conv1 out (fp16 bits)
__device__ unsigned short g_e2p[320 * 64 * 1024];      // encoder conv2 out (fp16 bits)
__device__ float          g_h  [BB * 64 * 1024];       // GRU hidden (fp32 master)
__device__ unsigned short g_hp [BB * 64 * 1024];       // h (fp16 bits)
__device__ float          g_z  [BB * 64 * 1024];       // z gate (fp32)
__device__ unsigned short g_rhp[BB * 64 * 1024];       // r*h (fp16 bits)
__device__ unsigned short g_hsp[TT * BB * 64 * 1024];  // decoder hidden outputs (fp16 bits)
__device__ unsigned short g_y1p[320 * 32 * 64 * 64];   // deconv1 out (fp16 bits)
__device__ __align__(16) unsigned short g_wp [921600]; // GRU W fragments, fp16
__device__ __align__(16) unsigned short g_wd1[32768];  // deconv1 W fragments, fp16
__device__ __align__(16) unsigned short g_we2[9216];   // enc_conv2 W fragments, fp16

__device__ __forceinline__ unsigned short h16(float v) {
    return __half_as_ushort(__float2half(v));
}

// ---------------- fused init: zero h/hp + pack GRU + deconv1 + enc_conv2 weights ----------------
// GRU layout: [tap][kc][ob][lane][r][e] fp16
__global__ void init_all(const float* __restrict__ ewzr, const float* __restrict__ ewc,
                         const float* __restrict__ dwzr, const float* __restrict__ dwc,
                         const float* __restrict__ dw1, const float* __restrict__ ew2) {
    long lidx = (long)blockIdx.x * 256 + threadIdx.x;
    if (lidx < 2097152) { g_h[lidx] = 0.f; g_hp[lidx] = 0; return; }
    int idx = (int)(lidx - 2097152);
    if (idx < 921600) {
        const float* w; int OC, IC, icoff, dofs;
        if (idx < 409600)      { w = ewzr; OC = 128; IC = 128; icoff = 0;  dofs = 0; }
        else if (idx < 614400) { idx -= 409600; w = ewc;  OC = 64;  IC = 128; icoff = 0;  dofs = 409600; }
        else if (idx < 819200) { idx -= 614400; w = dwzr; OC = 128; IC = 64;  icoff = 64; dofs = 614400; }
        else                   { idx -= 819200; w = dwc;  OC = 64;  IC = 64;  icoff = 64; dofs = 819200; }
        int KC = IC >> 4, NOB = OC >> 4;
        int e    = idx & 1;
        int r    = (idx >> 1) & 3;
        int lane = (idx >> 3) & 31;
        int v    = idx >> 8;
        int ob   = v % NOB;
        int v2   = v / NOB;
        int kc   = v2 % KC;
        int tap  = v2 / KC;
        int g = lane >> 2, t = lane & 3;
        int oc = ob * 16 + g + 8 * (r & 1);
        int ic = kc * 16 + 2 * t + 8 * (r >> 1) + e;
        g_wp[dofs + idx] = h16(w[(oc * 128 + icoff + ic) * 25 + tap]);
        return;
    }
    idx -= 921600;
    if (idx < 32768) {
        // deconv1 weights: [p][tt][kc][ob][lane][r][e]
        int e    = idx & 1;
        int r    = (idx >> 1) & 3;
        int lane = (idx >> 3) & 31;
        int ob   = (idx >> 8) & 1;
        int kc   = (idx >> 9) & 3;
        int tt   = (idx >> 11) & 3;
        int p    = (idx >> 13) & 3;
        int g = lane >> 2, tg = lane & 3;
        int oc = ob * 16 + g + 8 * (r & 1);
        int ic = kc * 16 + 2 * tg + 8 * (r >> 1) + e;
        int a = p >> 1, bb = p & 1, jy = tt >> 1, jx = tt & 1;
        int kidx = (a + 2 * jy) * 4 + (bb + 2 * jx);
        g_wd1[idx] = h16(dw1[(oc * 64 + ic) * 16 + kidx]);
        return;
    }
    idx -= 32768;
    if (idx < 9216) {
        // enc_conv2 weights: [tap][ob(4)][lane][r][e], K=16 (single kc)
        int e    = idx & 1;
        int r    = (idx >> 1) & 3;
        int lane = (idx >> 3) & 31;
        int ob   = (idx >> 8) & 3;
        int tap  = idx >> 10;          // 0..8
        int g = lane >> 2, tg = lane & 3;
        int oc = ob * 16 + g + 8 * (r & 1);
        int ic = 2 * tg + 8 * (r >> 1) + e;
        g_we2[idx] = h16(ew2[(oc * 16 + ic) * 9 + tap]);
    }
}

// ---------------- mma helper (fp16 in, fp32 accum) ----------------
__device__ __forceinline__ void mma_f16(float (&d)[4], const uint4& a, const unsigned (&b)[2]) {
    asm volatile(
        "mma.sync.aligned.m16n8k16.row.col.f32.f16.f16.f32 "
        "{%0,%1,%2,%3}, {%4,%5,%6,%7}, {%8,%9}, {%0,%1,%2,%3};\n"
        : "+f"(d[0]), "+f"(d[1]), "+f"(d[2]), "+f"(d[3])
        : "r"(a.x), "r"(a.y), "r"(a.z), "r"(a.w), "r"(b[0]), "r"(b[1]));
}

// ---------------- GRU 5x5 conv via mma.sync fp16; IC in 64-ch halves; warp tile MT x 4 ----------------
// mode: 0=enc zr (e2p ++ hp)  1=enc cand (e2p ++ rhp)  2=dec zr (hp)  3=dec cand (rhp)
// act_mode 0: sigmoid -> r->g_rhp, z->g_z; act_mode 1: tanh -> h update (+g_hsp fp16)
template <int NH, int MT>
__global__ __launch_bounds__(256, 2) void gru2(int t, int mode, int nob, int wofs,
                                               const float* __restrict__ bias,
                                               int act_mode, int write_hs) {
    extern __shared__ unsigned short Xs[];   // [288 px][72] fp16 bits

    int b   = blockIdx.x;
    int y0  = blockIdx.y * 4;
    int tid = threadIdx.x;
    int w   = tid >> 5, lane = tid & 31;
    int g   = lane >> 2, tg = lane & 3;
    int mw  = w >> 2, nw = w & 3;

    const unsigned short* s0p;
    const unsigned short* s1p;
    if (mode <= 1) {
        s0p = g_e2p + (b * 10 + t) * 65536;
        s1p = (mode == 0 ? g_hp : g_rhp) + b * 65536;
    } else {
        s0p = (mode == 2 ? g_hp : g_rhp) + b * 65536;
        s1p = s0p;
    }

    float D[MT][4][4];
#pragma unroll
    for (int mt = 0; mt < MT; mt++)
#pragma unroll
        for (int nt = 0; nt < 4; nt++)
#pragma unroll
            for (int i = 0; i < 4; i++) D[mt][nt][i] = 0.f;

    const uint4* pw = reinterpret_cast<const uint4*>(g_wp) + (wofs >> 3);
    const int KC = NH * 4;
    const int S1 = nob * 32;
    const int S2 = (KC - 3) * nob * 32;
    const int ob0 = mw * MT;

#pragma unroll 1
    for (int h = 0; h < NH; h++) {
        if (h) __syncthreads();
        // ---- stage 64-ch half: channel-pair packed, one pass, STS.32 conflict-free ----
        {
            const unsigned short* base = (h == 0) ? s0p : s1p;
            int cp = tid & 31;
            int sy = tid >> 5;
            int yy = y0 - 2 + sy;
            bool rv = (unsigned)yy < 32u;
            const uint4* p0 = (const uint4*)(base + (2 * cp) * 1024 + yy * 32);
            const uint4* p1 = (const uint4*)(base + (2 * cp + 1) * 1024 + yy * 32);
            uint4 q0[4], q1[4];
            if (rv) {
#pragma unroll
                for (int k2 = 0; k2 < 4; k2++) { q0[k2] = p0[k2]; q1[k2] = p1[k2]; }
            } else {
#pragma unroll
                for (int k2 = 0; k2 < 4; k2++) {
                    q0[k2] = make_uint4(0u, 0u, 0u, 0u);
                    q1[k2] = make_uint4(0u, 0u, 0u, 0u);
                }
            }
            const unsigned short* h0 = (const unsigned short*)q0;
            const unsigned short* h1 = (const unsigned short*)q1;
            unsigned* Xw = (unsigned*)Xs;
            int rb = sy * 36;
#pragma unroll
            for (int sx = 0; sx < 36; sx++) {
                unsigned v = 0u;
                if (sx >= 2 && sx < 34) {
                    int x = sx - 2;
                    v = (unsigned)h0[x] | ((unsigned)h1[x] << 16);
                }
                Xw[(rb + sx) * 36 + cp] = v;
            }
        }
        __syncthreads();

        // ---- MMA over taps x 4 kch (A-prefetch only) ----
        int fb = (h * 4 * nob + ob0) * 32 + lane;
        uint4 ah[MT];
#pragma unroll
        for (int mt = 0; mt < MT; mt++) ah[mt] = pw[fb + mt * 32];
#pragma unroll 1
        for (int tap = 0; tap < 25; tap++) {
            int dy = tap / 5, dx = tap - 5 * dy;
            int rowbase = ((nw + dy) * 36 + dx) * 72;
#pragma unroll
            for (int kch = 0; kch < 4; kch++) {
                int fn = (tap == 24 && kch == 3) ? fb : fb + (kch < 3 ? S1 : S2);
                uint4 nah[MT];
#pragma unroll
                for (int mt = 0; mt < MT; mt++) nah[mt] = pw[fn + mt * 32];
                unsigned Bs[4][2];
#pragma unroll
                for (int nt = 0; nt < 4; nt++) {
                    int off = rowbase + (nt * 8 + g) * 72 + kch * 16 + 2 * tg;
                    Bs[nt][0] = *(const unsigned*)(Xs + off);
                    Bs[nt][1] = *(const unsigned*)(Xs + off + 8);
                }
#pragma unroll
                for (int mt = 0; mt < MT; mt++)
#pragma unroll
                    for (int nt = 0; nt < 4; nt++) mma_f16(D[mt][nt], ah[mt], Bs[nt]);
#pragma unroll
                for (int mt = 0; mt < MT; mt++) ah[mt] = nah[mt];
                fb = fn;
            }
        }
    }

    // ---- fused epilogue ----
    int y = y0 + nw;
#pragma unroll
    for (int mt = 0; mt < MT; mt++) {
#pragma unroll
        for (int ci2 = 0; ci2 < 2; ci2++) {
            int   ocG = (ob0 + mt) * 16 + g + 8 * ci2;
            float bv  = bias[ocG];
#pragma unroll
            for (int nt = 0; nt < 4; nt++) {
#pragma unroll
                for (int j = 0; j < 2; j++) {
                    float v  = D[mt][nt][ci2 * 2 + j] + bv;
                    int   x  = nt * 8 + 2 * tg + j;
                    int   px = y * 32 + x;
                    if (act_mode == 0) {
                        float s = 1.f / (1.f + expf(-v));
                        if (ocG < 64) {
                            int hi = (b * 64 + ocG) * 1024 + px;
                            g_rhp[hi] = h16(s * g_h[hi]);
                        } else {
                            g_z[(b * 64 + ocG - 64) * 1024 + px] = s;
                        }
                    } else {
                        float c  = tanhf(v);
                        int   hi = (b * 64 + ocG) * 1024 + px;
                        float z  = g_z[hi];
                        float hp = g_h[hi];
                        float hn = (1.f - z) * hp + z * c;
                        g_h[hi]  = hn;
                        g_hp[hi] = h16(hn);
                        if (write_hs) g_hsp[t * 2097152 + hi] = h16(hn);
                    }
                }
            }
        }
    }
}

// ---------------- enc_conv2 via mma.sync fp16: 16->64 ch, 3x3 s2 p1, 64->32, lrelu ----------------
// CTA: (n, 4-row output strip). 8 warps (mw 0..1, nw 0..3), MT=2 -> OC=64. K=16 per tap, 9 taps.
__global__ __launch_bounds__(256) void enc_conv2_tc(const float* __restrict__ bias) {
    __shared__ unsigned Xw[9 * 66 * 8];      // [lr 0..8][lc 0..65][cp 0..7] packed ch-pairs
    int n   = blockIdx.x;
    int oy0 = blockIdx.y * 4;
    int tid = threadIdx.x;
    int w   = tid >> 5, lane = tid & 31;
    int g   = lane >> 2, tg = lane & 3;
    int mw  = w >> 2, nw = w & 3;

    // ---- stage input rows 2*oy0-1 .. 2*oy0+7, cols -1..64, 16 ch ----
    if (tid < 72) {
        int lr = tid >> 3, cp = tid & 7;
        int iy = 2 * oy0 - 1 + lr;
        bool rv = (unsigned)iy < 64u;
        const unsigned short* base = g_e1p + n * 65536;
        const uint4* p0 = (const uint4*)(base + (2 * cp) * 4096 + iy * 64);
        const uint4* p1 = (const uint4*)(base + (2 * cp + 1) * 4096 + iy * 64);
        uint4 q0[8], q1[8];
        if (rv) {
#pragma unroll
            for (int k2 = 0; k2 < 8; k2++) { q0[k2] = p0[k2]; q1[k2] = p1[k2]; }
        } else {
#pragma unroll
            for (int k2 = 0; k2 < 8; k2++) {
                q0[k2] = make_uint4(0u, 0u, 0u, 0u);
                q1[k2] = make_uint4(0u, 0u, 0u, 0u);
            }
        }
        const unsigned short* h0 = (const unsigned short*)q0;
        const unsigned short* h1 = (const unsigned short*)q1;
        int rb = lr * 66;
        Xw[rb * 8 + cp] = 0u;
        Xw[(rb + 65) * 8 + cp] = 0u;
#pragma unroll
        for (int x = 0; x < 64; x++)
            Xw[(rb + 1 + x) * 8 + cp] = (unsigned)h0[x] | ((unsigned)h1[x] << 16);
    }
    __syncthreads();

    float D[2][4][4];
#pragma unroll
    for (int mt = 0; mt < 2; mt++)
#pragma unroll
        for (int nt = 0; nt < 4; nt++)
#pragma unroll
            for (int i = 0; i < 4; i++) D[mt][nt][i] = 0.f;

    const uint4* wd = reinterpret_cast<const uint4*>(g_we2);
#pragma unroll
    for (int tap = 0; tap < 9; tap++) {
        int ky = tap / 3, kx = tap - 3 * ky;
        uint4 a0 = wd[(tap * 4 + mw * 2 + 0) * 32 + lane];
        uint4 a1 = wd[(tap * 4 + mw * 2 + 1) * 32 + lane];
        int lr = 2 * nw + ky;
        unsigned Bs[4][2];
#pragma unroll
        for (int nt = 0; nt < 4; nt++) {
            int lc  = 2 * (nt * 8 + g) + kx;
            int off = (lr * 66 + lc) * 8;
            Bs[nt][0] = Xw[off + tg];
            Bs[nt][1] = Xw[off + 4 + tg];
        }
#pragma unroll
        for (int nt = 0; nt < 4; nt++) {
            mma_f16(D[0][nt], a0, Bs[nt]);
            mma_f16(D[1][nt], a1, Bs[nt]);
        }
    }

    // ---- epilogue: lrelu, emit fp16 ----
    int oy = oy0 + nw;
#pragma unroll
    for (int mt = 0; mt < 2; mt++) {
#pragma unroll
        for (int ci2 = 0; ci2 < 2; ci2++) {
            int oc = (mw * 2 + mt) * 16 + g + 8 * ci2;
            float bv = bias[oc];
#pragma unroll
            for (int nt = 0; nt < 4; nt++) {
#pragma unroll
                for (int j = 0; j < 2; j++) {
                    float v = D[mt][nt][ci2 * 2 + j] + bv;
                    v = (v >= 0.f) ? v : 0.2f * v;
                    int ox = nt * 8 + 2 * tg + j;
                    g_e2p[(n * 64 + oc) * 1024 + oy * 32 + ox] = h16(v);
                }
            }
        }
    }
}

// ---------------- deconv1 via mma.sync fp16: 64->32, 4x4 lhs_dil 2 pad 2, 4 parity 2x2 convs ----------------
__global__ __launch_bounds__(128) void deconv1_tc(const float* __restrict__ bias) {
    __shared__ unsigned short Xs[6 * 34 * 72];
    int n   = blockIdx.x;
    int y0  = blockIdx.y * 4;
    int tid = threadIdx.x;
    int w   = tid >> 5, lane = tid & 31;
    int g   = lane >> 2, tg = lane & 3;
    int nw  = w;

    // ---- stage: channel-pair packed STS.32 ----
    const unsigned short* in = g_hsp + n * 65536;
    {
        int cp = tid & 31;
        int r0 = tid >> 5;
        unsigned* Xw = (unsigned*)Xs;
#pragma unroll
        for (int rr = 0; rr < 2; rr++) {
            int row = r0 + rr * 4;
            if (row < 6) {
                int yy = y0 - 1 + row;
                bool rv = (unsigned)yy < 32u;
                const uint4* p0 = (const uint4*)(in + (2 * cp) * 1024 + yy * 32);
                const uint4* p1 = (const uint4*)(in + (2 * cp + 1) * 1024 + yy * 32);
                uint4 q0[4], q1[4];
                if (rv) {
#pragma unroll
                    for (int k2 = 0; k2 < 4; k2++) { q0[k2] = p0[k2]; q1[k2] = p1[k2]; }
                } else {
#pragma unroll
                    for (int k2 = 0; k2 < 4; k2++) {
                        q0[k2] = make_uint4(0u, 0u, 0u, 0u);
                        q1[k2] = make_uint4(0u, 0u, 0u, 0u);
                    }
                }
                const unsigned short* h0 = (const unsigned short*)q0;
                const unsigned short* h1 = (const unsigned short*)q1;
                int rb = row * 34;
                Xw[rb * 36 + cp] = 0u;
                Xw[(rb + 33) * 36 + cp] = 0u;
#pragma unroll
                for (int x = 0; x < 32; x++)
                    Xw[(rb + 1 + x) * 36 + cp] = (unsigned)h0[x] | ((unsigned)h1[x] << 16);
            }
        }
    }
    __syncthreads();

    const uint4* wd = reinterpret_cast<const uint4*>(g_wd1);

#pragma unroll 1
    for (int p = 0; p < 4; p++) {
        int a = p >> 1, bp = p & 1;
        float D[2][4][4];
#pragma unroll
        for (int mt = 0; mt < 2; mt++)
#pragma unroll
            for (int nt = 0; nt < 4; nt++)
#pragma unroll
                for (int i = 0; i < 4; i++) D[mt][nt][i] = 0.f;

#pragma unroll
        for (int tt = 0; tt < 4; tt++) {
            int jy = tt >> 1, jx = tt & 1;
            int rowbase = ((nw + a + jy) * 34 + (bp + jx)) * 72;
#pragma unroll
            for (int kc = 0; kc < 4; kc++) {
                uint4 a0 = wd[((((p * 4 + tt) * 4 + kc) * 2 + 0) * 32) + lane];
                uint4 a1 = wd[((((p * 4 + tt) * 4 + kc) * 2 + 1) * 32) + lane];
                unsigned Bs[4][2];
#pragma unroll
                for (int nt = 0; nt < 4; nt++) {
                    int off = rowbase + (nt * 8 + g) * 72 + kc * 16 + 2 * tg;
                    Bs[nt][0] = *(const unsigned*)(Xs + off);
                    Bs[nt][1] = *(const unsigned*)(Xs + off + 8);
                }
#pragma unroll
                for (int nt = 0; nt < 4; nt++) {
                    mma_f16(D[0][nt], a0, Bs[nt]);
                    mma_f16(D[1][nt], a1, Bs[nt]);
                }
            }
        }

        int oy = 2 * (y0 + nw) + a;
#pragma unroll
        for (int mt = 0; mt < 2; mt++) {
#pragma unroll
            for (int ci2 = 0; ci2 < 2; ci2++) {
                int oc = mt * 16 + g + 8 * ci2;
                float bv = bias[oc];
#pragma unroll
                for (int nt = 0; nt < 4; nt++) {
#pragma unroll
                    for (int j = 0; j < 2; j++) {
                        float v = D[mt][nt][ci2 * 2 + j] + bv;
                        v = (v >= 0.f) ? v : 0.2f * v;
                        int ox = 2 * (nt * 8 + 2 * tg + j) + bp;
                        g_y1p[(n * 32 + oc) * 4096 + oy * 64 + ox] = h16(v);
                    }
                }
            }
        }
    }
}

// ---------------- encoder conv1: 1->16, 3x3 s2 p1, lrelu, emit fp16 ----------------
__global__ __launch_bounds__(256) void enc_conv1(const float* __restrict__ x,
                                                 const float* __restrict__ w,
                                                 const float* __restrict__ bias) {
    __shared__ float sw[144], sb[16];
    int tid = threadIdx.x;
    if (tid < 144) sw[tid] = w[tid];
    if (tid < 16)  sb[tid] = bias[tid];
    __syncthreads();
    int n = blockIdx.x, p = blockIdx.y * 256 + tid;
    int oy = p >> 6, ox = p & 63;
    const float* xi = x + n * 16384;
    float win[9];
    int iy0 = 2 * oy - 1, ix0 = 2 * ox - 1;
#pragma unroll
    for (int ky = 0; ky < 3; ky++)
#pragma unroll
        for (int kx = 0; kx < 3; kx++) {
            int iy = iy0 + ky, ix = ix0 + kx;
            win[ky * 3 + kx] = ((unsigned)iy < 128u && (unsigned)ix < 128u) ? xi[iy * 128 + ix] : 0.f;
        }
#pragma unroll
    for (int oc = 0; oc < 16; oc++) {
        float a = sb[oc];
#pragma unroll
        for (int k = 0; k < 9; k++) a += sw[oc * 9 + k] * win[k];
        a = (a >= 0.f) ? a : 0.2f * a;
        g_e1p[(n * 16 + oc) * 4096 + p] = h16(a);
    }
}

// ---------------- deconv2: 32->1, 4x4 lhs_dil 2 pad 2, fp16 in, + transpose ----------------
__global__ __launch_bounds__(256) void deconv2(const float* __restrict__ w,
                                               const float* __restrict__ bias,
                                               float* __restrict__ out) {
    __shared__ float sw[512];
    int tid = threadIdx.x;
    for (int i = tid; i < 512; i += 256) sw[i] = w[i];
    __syncthreads();
    int n = blockIdx.x, p = blockIdx.y * 256 + tid;
    int oy = p >> 7, ox = p & 127;
    int ky0 = oy & 1, kx0 = ox & 1;
    int iyA = (oy + ky0 - 2) >> 1, iyB = iyA + 1;
    int ixA = (ox + kx0 - 2) >> 1, ixB = ixA + 1;
    bool yA = (unsigned)iyA < 64u, yB = (unsigned)iyB < 64u;
    bool xA = (unsigned)ixA < 64u, xB = (unsigned)ixB < 64u;
    const unsigned short* in = g_y1p + n * 131072;
    float acc = bias[0];
#pragma unroll 1
    for (int ic = 0; ic < 32; ic++) {
        const unsigned short* ip = in + ic * 4096;
        float vAA = (yA && xA) ? __half2float(__ushort_as_half(ip[iyA * 64 + ixA])) : 0.f;
        float vAB = (yA && xB) ? __half2float(__ushort_as_half(ip[iyA * 64 + ixB])) : 0.f;
        float vBA = (yB && xA) ? __half2float(__ushort_as_half(ip[iyB * 64 + ixA])) : 0.f;
        float vBB = (yB && xB) ? __half2float(__ushort_as_half(ip[iyB * 64 + ixB])) : 0.f;
        const float* wp = &sw[ic * 16];
        acc += wp[ky0 * 4 + kx0] * vAA + wp[ky0 * 4 + kx0 + 2] * vAB
             + wp[(ky0 + 2) * 4 + kx0] * vBA + wp[(ky0 + 2) * 4 + kx0 + 2] * vBB;
    }
    int t = n >> 5, b = n & 31;
    out[(b * 10 + t) * 16384 + p] = acc;
}

// ---------------- launch ----------------
extern "C" void kernel_launch(void* const* d_in, const int* in_sizes, int n_in,
                              void* d_out, int out_size) {
    const float* x           = (const float*)d_in[0];
    const float* enc_w1      = (const float*)d_in[1];
    const float* enc_b1      = (const float*)d_in[2];
    const float* enc_w2      = (const float*)d_in[3];
    const float* enc_b2      = (const float*)d_in[4];
    const float* enc_gru_wzr = (const float*)d_in[5];
    const float* enc_gru_bzr = (const float*)d_in[6];
    const float* enc_gru_wc  = (const float*)d_in[7];
    const float* enc_gru_bc  = (const float*)d_in[8];
    const float* dec_gru_wzr = (const float*)d_in[9];
    const float* dec_gru_bzr = (const float*)d_in[10];
    const float* dec_gru_wc  = (const float*)d_in[11];
    const float* dec_gru_bc  = (const float*)d_in[12];
    const float* dec_w1      = (const float*)d_in[13];
    const float* dec_b1      = (const float*)d_in[14];
    const float* dec_w2      = (const float*)d_in[15];
    const float* dec_b2      = (const float*)d_in[16];
    float* out = (float*)d_out;

    const int SMB = 288 * 72 * 2;   // 41472 B fp16 X tile
    cudaFuncSetAttribute((gru2<2, 4>), cudaFuncAttributeMaxDynamicSharedMemorySize, SMB);
    cudaFuncSetAttribute((gru2<2, 2>), cudaFuncAttributeMaxDynamicSharedMemorySize, SMB);
    cudaFuncSetAttribute((gru2<1, 4>), cudaFuncAttributeMaxDynamicSharedMemorySize, SMB);
    cudaFuncSetAttribute((gru2<1, 2>), cudaFuncAttributeMaxDynamicSharedMemorySize, SMB);

    init_all<<<(2097152 + 921600 + 32768 + 9216 + 255) / 256, 256>>>(
        enc_gru_wzr, enc_gru_wc, dec_gru_wzr, dec_gru_wc, dec_w1, enc_w2);    // #1
    enc_conv1<<<dim3(320, 16), 256>>>(x, enc_w1, enc_b1);                     // #2
    enc_conv2_tc<<<dim3(320, 8), 256>>>(enc_b2);                              // #3

    for (int t = 0; t < 10; t++) {                                            // #4,#5,#6(captured)...
        gru2<2, 4><<<dim3(32, 8), 256, SMB>>>(t, 0, 8, 0, enc_gru_bzr, 0, 0);
        gru2<2, 2><<<dim3(32, 8), 256, SMB>>>(t, 1, 4, 409600, enc_gru_bc, 1, 0);
    }
    for (int t = 0; t < 10; t++) {
        gru2<1, 4><<<dim3(32, 8), 256, SMB>>>(t, 2, 8, 614400, dec_gru_bzr, 0, 0);
        gru2<1, 2><<<dim3(32, 8), 256, SMB>>>(t, 3, 4, 819200, dec_gru_bc, 1, 1);
    }

    deconv1_tc<<<dim3(320, 8), 128>>>(dec_b1);
    deconv2<<<dim3(320, 64), 256>>>(dec_w2, dec_b2, out);
}